// round 12
// baseline (speedup 1.0000x reference)
#include <cuda_runtime.h>
#include <cuda_fp16.h>
#include <cstdint>
#include <cstddef>

#define BROWS 32768
#define DIN   256
#define UNITS 512

static constexpr float DT  = 1.0f / 6.0f;
static constexpr float DT2 = DT * 0.5f;
static constexpr float DT3 = DT / 3.0f;
static constexpr float DT6 = DT / 6.0f;

// ------------------------------------------------------------------ scratch
__device__ alignas(16) float  g_XKb[(size_t)BROWS * UNITS];
__device__ alignas(16) float  g_S  [(size_t)BROWS * UNITS];
__device__ alignas(16) __half g_H0h[(size_t)BROWS * UNITS];
__device__ alignas(16) __half g_H0l[(size_t)BROWS * UNITS];
__device__ alignas(16) __half g_HAh[(size_t)BROWS * UNITS];
__device__ alignas(16) __half g_HAl[(size_t)BROWS * UNITS];
__device__ alignas(16) __half g_HBh[(size_t)BROWS * UNITS];
__device__ alignas(16) __half g_HBl[(size_t)BROWS * UNITS];
__device__ alignas(16) __half g_Xh [(size_t)BROWS * DIN];
__device__ alignas(16) __half g_Xl [(size_t)BROWS * DIN];
__device__ alignas(16) __half g_Rth[UNITS * UNITS];
__device__ alignas(16) __half g_Kth[UNITS * DIN];

// ------------------------------------------------------------------ helpers
__device__ __forceinline__ uint32_t smem_u32(const void* p) {
    uint32_t a;
    asm("{ .reg .u64 t; cvta.to.shared.u64 t, %1; cvt.u32.u64 %0, t; }" : "=r"(a) : "l"(p));
    return a;
}

__device__ __forceinline__ void cp_async16(uint32_t saddr, const void* gaddr) {
    asm volatile("cp.async.cg.shared.global [%0], [%1], 16;" :: "r"(saddr), "l"(gaddr));
}
#define CP_COMMIT() asm volatile("cp.async.commit_group;" ::: "memory")
#define CP_WAIT(n)  asm volatile("cp.async.wait_group %0;" :: "n"(n) : "memory")

__device__ __forceinline__ void pf_l2(const void* p) {
    asm volatile("prefetch.global.L2 [%0];" :: "l"(p));
}

__device__ __forceinline__ void ldsm_x4(uint32_t addr, uint32_t& r0, uint32_t& r1,
                                        uint32_t& r2, uint32_t& r3) {
    asm volatile("ldmatrix.sync.aligned.m8n8.x4.shared.b16 {%0,%1,%2,%3}, [%4];"
                 : "=r"(r0), "=r"(r1), "=r"(r2), "=r"(r3) : "r"(addr));
}

__device__ __forceinline__ void mma16816(float* c, const uint32_t* a,
                                         uint32_t b0, uint32_t b1) {
    asm volatile("mma.sync.aligned.m16n8k16.row.col.f32.f16.f16.f32 "
                 "{%0,%1,%2,%3}, {%4,%5,%6,%7}, {%8,%9}, {%0,%1,%2,%3};"
                 : "+f"(c[0]), "+f"(c[1]), "+f"(c[2]), "+f"(c[3])
                 : "r"(a[0]), "r"(a[1]), "r"(a[2]), "r"(a[3]), "r"(b0), "r"(b1));
}

__device__ __forceinline__ float tanh_fast(float x) {
    const float e = __expf(2.0f * x);
    return 1.0f - 2.0f / (e + 1.0f);
}

__device__ __forceinline__ void hsplit2(__half* ph, __half* pl, float v0, float v1) {
    const __half h0 = __float2half(v0);
    const __half h1 = __float2half(v1);
    const __half l0 = __float2half(v0 - __half2float(h0));
    const __half l1 = __float2half(v1 - __half2float(h1));
    __half2 hh; hh.x = h0; hh.y = h1;
    __half2 ll; ll.x = l0; ll.y = l1;
    *reinterpret_cast<__half2*>(ph) = hh;
    *reinterpret_cast<__half2*>(pl) = ll;
}

// ------------------------------------------------------------------ smem map (dynamic)
static constexpr uint32_t TILE_BYTES = 128 * 128;         // 128 rows x 128B (64 halfs)
static constexpr uint32_t OFF_A0  = 0;
static constexpr uint32_t OFF_A1  = OFF_A0 + TILE_BYTES;  // 16384
static constexpr uint32_t OFF_B0  = OFF_A1 + TILE_BYTES;  // 32768
static constexpr uint32_t OFF_B1  = OFF_B0 + TILE_BYTES;  // 49152
static constexpr uint32_t OFF_SCL = OFF_B1 + TILE_BYTES;  // 65536
static constexpr uint32_t SMEM_BYTES = OFF_SCL + 512 + 16;   // 66.1 KB -> 3 CTAs/SM fits

// ------------------------------------------------------------------ main GEMM + RK4 epilogue
// NPASS=2: [A_hi | A_lo] @ [B_hi | B_hi]  — used for x@K (once)
// NPASS=1: A_hi @ B_hi                    — stage GEMMs (~1.8e-4 total err)
// __launch_bounds__(256,3): regs capped at 85 so 3 CTAs/SM co-reside
// (R10 profile: regs=128 -> 2 CTAs, occ 22%, issue 20%, nothing saturated
//  -> latency-bound; third CTA buys 50% more latency-hiding warps).
template <int MODE, int KSEG, int NPASS, bool LAST>
__global__ void __launch_bounds__(256, 3)
ctrnn_gemm(const float* __restrict__ sb, float* __restrict__ outp) {
    extern __shared__ char smem[];
    const uint32_t sbase = smem_u32(smem);
    const int tid  = threadIdx.x;
    const int lane = tid & 31;
    const int wid  = tid >> 5;
    const int warpM = (wid & 3) * 32;        // 4 warps along M
    const int warpN = (wid >> 2) * 64;       // 2 warps along N
    const int rowBase = blockIdx.y * 128;
    const int nBase   = blockIdx.x * 128;

    constexpr int CHPS = KSEG / 64;
    constexpr int NCH  = NPASS * CHPS;

    const __half *Ah, *Al, *Bh;
    if constexpr (MODE == 0)      { Ah = g_Xh;  Al = g_Xl;  Bh = g_Kth; }
    else if constexpr (MODE == 1) { Ah = g_H0h; Al = g_H0l; Bh = g_Rth; }
    else if constexpr (MODE == 2) { Ah = g_HAh; Al = g_HAl; Bh = g_Rth; }
    else if constexpr (MODE == 3) { Ah = g_HBh; Al = g_HBl; Bh = g_Rth; }
    else                          { Ah = g_HAh; Al = g_HAl; Bh = g_Rth; }

    __half *nxh = nullptr, *nxl = nullptr;
    if constexpr (MODE == 1)               { nxh = g_HAh; nxl = g_HAl; }
    else if constexpr (MODE == 2)          { nxh = g_HBh; nxl = g_HBl; }
    else if constexpr (MODE == 3)          { nxh = g_HAh; nxl = g_HAl; }
    else if constexpr (MODE == 4 && !LAST) { nxh = g_H0h; nxl = g_H0l; }

    if (tid < 128)
        reinterpret_cast<float*>(smem + OFF_SCL)[tid] = sb[nBase + tid];

    const __half* Aseg[2] = {Ah, (NPASS == 2) ? Al : Ah};

    // slot mapping for cp.async: 1024 slots per tile (128 rows x 8 col16)
    const int srow = tid >> 3;
    const int scol = tid & 7;

    auto load_chunk = [&](int c, int buf) {
        const int seg = c / CHPS;
        const int kof = (c % CHPS) * 64;
        const __half* As = Aseg[seg];
        const __half* Bs = Bh;
        const uint32_t aOff = buf ? OFF_A1 : OFF_A0;
        const uint32_t bOff = buf ? OFF_B1 : OFF_B0;
#pragma unroll
        for (int i = 0; i < 4; ++i) {
            const int r = srow + i * 32;
            uint32_t off = (uint32_t)(r * 128 + ((scol ^ (r & 7)) << 4));
            cp_async16(sbase + aOff + off,
                       As + (size_t)(rowBase + r) * KSEG + kof + scol * 8);
        }
#pragma unroll
        for (int i = 0; i < 4; ++i) {
            const int r = srow + i * 32;
            uint32_t off = (uint32_t)(r * 128 + ((scol ^ (r & 7)) << 4));
            cp_async16(sbase + bOff + off,
                       Bs + (size_t)(nBase + r) * KSEG + kof + scol * 8);
        }
        CP_COMMIT();
    };

    // L2 prefetch helpers for this CTA's 128x128 epilogue tile.
    auto pf_f32 = [&](const float* base) {
        const int L0 = tid;            // 512 lines of 128B, 2/thread
        pf_l2(base + (size_t)(rowBase + (L0 >> 2)) * UNITS + nBase + (L0 & 3) * 32);
        const int L1 = tid + 256;
        pf_l2(base + (size_t)(rowBase + (L1 >> 2)) * UNITS + nBase + (L1 & 3) * 32);
    };
    auto pf_f16 = [&](const __half* base) {
        const int L = tid;             // 256 lines, 1/thread
        pf_l2(base + (size_t)(rowBase + (L >> 1)) * UNITS + nBase + (L & 1) * 64);
    };

    float acc[2][8][4];
#pragma unroll
    for (int mf = 0; mf < 2; ++mf)
#pragma unroll
        for (int nf = 0; nf < 8; ++nf)
#pragma unroll
            for (int i = 0; i < 4; ++i) acc[mf][nf][i] = 0.0f;

    // 2-stage pipeline: one barrier per chunk; L(c+1) overlaps MMA(c).
    load_chunk(0, 0);

    for (int c = 0; c < NCH; ++c) {
        CP_WAIT(0);
        __syncthreads();
        if (c + 1 < NCH) load_chunk(c + 1, (c + 1) & 1);

        // LATE prefetch of epilogue operands (close to use; avoids L2 thrash)
        if constexpr (MODE != 0) {
            if (c == NCH - 3) {
                pf_f32(g_XKb);
                pf_f16(Al);
            } else if (c == NCH - 2) {
                if constexpr (MODE >= 2) pf_f32(g_S);
                if constexpr (MODE == 2 || MODE == 3) { pf_f16(g_H0h); pf_f16(g_H0l); }
            }
        }

        const uint32_t aBase = sbase + ((c & 1) ? OFF_A1 : OFF_A0);
        const uint32_t bBase = sbase + ((c & 1) ? OFF_B1 : OFF_B0);
#pragma unroll
        for (int q = 0; q < 4; ++q) {
            uint32_t a[2][4];
#pragma unroll
            for (int mf = 0; mf < 2; ++mf) {
                const int row = warpM + mf * 16 + ((lane >> 3) & 1) * 8 + (lane & 7);
                const int c16 = q * 2 + (lane >> 4);
                const uint32_t addr = aBase + row * 128 + (((c16 ^ (row & 7)) & 7) << 4);
                ldsm_x4(addr, a[mf][0], a[mf][1], a[mf][2], a[mf][3]);
            }
#pragma unroll
            for (int g = 0; g < 4; ++g) {
                uint32_t b0, b1, b2, b3;
                const int row = warpN + g * 16 + ((lane >> 3) & 1) * 8 + (lane & 7);
                const int c16 = q * 2 + (lane >> 4);
                const uint32_t addr = bBase + row * 128 + (((c16 ^ (row & 7)) & 7) << 4);
                ldsm_x4(addr, b0, b1, b2, b3);
#pragma unroll
                for (int mf = 0; mf < 2; ++mf) {
                    mma16816(acc[mf][2 * g],     a[mf], b0, b2);
                    mma16816(acc[mf][2 * g + 1], a[mf], b1, b3);
                }
            }
        }
    }

    // ---------------- RK4 epilogue ----------------
    const float* scl = reinterpret_cast<const float*>(smem + OFF_SCL);

#pragma unroll
    for (int mf = 0; mf < 2; ++mf) {
#pragma unroll
        for (int nf = 0; nf < 8; ++nf) {
#pragma unroll
            for (int half_ = 0; half_ < 2; ++half_) {
                const int row = rowBase + warpM + mf * 16 + (lane >> 2) + half_ * 8;
                const int lc  = warpN + nf * 8 + (lane & 3) * 2;   // local col 0..127
                const int col = nBase + lc;
                const float c0 = acc[mf][nf][half_ * 2 + 0];
                const float c1 = acc[mf][nf][half_ * 2 + 1];
                const size_t eb = (size_t)row * UNITS + col;

                if constexpr (MODE == 0) {
                    float2 o;
                    o.x = c0 + scl[lc];
                    o.y = c1 + scl[lc + 1];
                    *reinterpret_cast<float2*>(g_XKb + eb) = o;
                } else {
                    const float2 xk = *reinterpret_cast<const float2*>(g_XKb + eb);
                    const __half2 ah = *reinterpret_cast<const __half2*>(Ah + eb);
                    const __half2 al = *reinterpret_cast<const __half2*>(Al + eb);
                    const float hs0 = __half2float(ah.x) + __half2float(al.x);
                    const float hs1 = __half2float(ah.y) + __half2float(al.y);
                    const float k0 = scl[lc]     * tanh_fast(c0 + xk.x) - hs0;
                    const float k1 = scl[lc + 1] * tanh_fast(c1 + xk.y) - hs1;

                    if constexpr (MODE == 1) {
                        hsplit2(nxh + eb, nxl + eb, hs0 + DT2 * k0, hs1 + DT2 * k1);
                        float2 sv; sv.x = hs0 + DT6 * k0; sv.y = hs1 + DT6 * k1;
                        *reinterpret_cast<float2*>(g_S + eb) = sv;
                    } else if constexpr (MODE == 2 || MODE == 3) {
                        const __half2 h0a = *reinterpret_cast<const __half2*>(g_H0h + eb);
                        const __half2 h0b = *reinterpret_cast<const __half2*>(g_H0l + eb);
                        const float h00 = __half2float(h0a.x) + __half2float(h0b.x);
                        const float h01 = __half2float(h0a.y) + __half2float(h0b.y);
                        const float2 s = *reinterpret_cast<const float2*>(g_S + eb);
                        constexpr float HC = (MODE == 2) ? DT2 : DT;
                        hsplit2(nxh + eb, nxl + eb, h00 + HC * k0, h01 + HC * k1);
                        float2 sn; sn.x = s.x + DT3 * k0; sn.y = s.y + DT3 * k1;
                        *reinterpret_cast<float2*>(g_S + eb) = sn;
                    } else {  // MODE 4
                        const float2 s = *reinterpret_cast<const float2*>(g_S + eb);
                        const float f0 = s.x + DT6 * k0;
                        const float f1 = s.y + DT6 * k1;
                        if constexpr (LAST) {
                            float2 o; o.x = f0; o.y = f1;
                            *reinterpret_cast<float2*>(outp + eb) = o;
                        } else {
                            hsplit2(nxh + eb, nxl + eb, f0, f1);
                        }
                    }
                }
            }
        }
    }
}

// ------------------------------------------------------------------ fused prep kernel
__global__ void prep_all_kernel(const float* __restrict__ h, const float* __restrict__ x,
                                const float* __restrict__ Rm, const float* __restrict__ Km) {
    const int i = blockIdx.x * blockDim.x + threadIdx.x;
    {
        const int nA = BROWS * UNITS / 4;
        if (i < nA) {
            const float4 v = reinterpret_cast<const float4*>(h)[i];
            hsplit2(g_H0h + (size_t)i * 4,     g_H0l + (size_t)i * 4,     v.x, v.y);
            hsplit2(g_H0h + (size_t)i * 4 + 2, g_H0l + (size_t)i * 4 + 2, v.z, v.w);
        }
    }
    {
        const int nB = BROWS * DIN / 4;
        if (i < nB) {
            const float4 v = reinterpret_cast<const float4*>(x)[i];
            hsplit2(g_Xh + (size_t)i * 4,     g_Xl + (size_t)i * 4,     v.x, v.y);
            hsplit2(g_Xh + (size_t)i * 4 + 2, g_Xl + (size_t)i * 4 + 2, v.z, v.w);
        }
    }
    {
        const int nC = UNITS * UNITS;
        if (i < nC) {
            const int k = i / UNITS, n = i % UNITS;
            g_Rth[(size_t)n * UNITS + k] = __float2half(Rm[i]);
        }
    }
    {
        const int nD = DIN * UNITS;
        if (i < nD) {
            const int k = i / UNITS, n = i % UNITS;
            g_Kth[(size_t)n * DIN + k] = __float2half(Km[i]);
        }
    }
}

// ------------------------------------------------------------------ launch
extern "C" void kernel_launch(void* const* d_in, const int* in_sizes, int n_in,
                              void* d_out, int out_size) {
    const float* x     = (const float*)d_in[0];
    const float* h     = (const float*)d_in[1];
    const float* Km    = (const float*)d_in[2];
    const float* Rm    = (const float*)d_in[3];
    const float* bias  = (const float*)d_in[4];
    const float* scale = (const float*)d_in[5];
    float* out = (float*)d_out;

    cudaFuncSetAttribute(ctrnn_gemm<0, 256, 2, false>, cudaFuncAttributeMaxDynamicSharedMemorySize, SMEM_BYTES);
    cudaFuncSetAttribute(ctrnn_gemm<1, 512, 1, false>, cudaFuncAttributeMaxDynamicSharedMemorySize, SMEM_BYTES);
    cudaFuncSetAttribute(ctrnn_gemm<2, 512, 1, false>, cudaFuncAttributeMaxDynamicSharedMemorySize, SMEM_BYTES);
    cudaFuncSetAttribute(ctrnn_gemm<3, 512, 1, false>, cudaFuncAttributeMaxDynamicSharedMemorySize, SMEM_BYTES);
    cudaFuncSetAttribute(ctrnn_gemm<4, 512, 1, false>, cudaFuncAttributeMaxDynamicSharedMemorySize, SMEM_BYTES);
    cudaFuncSetAttribute(ctrnn_gemm<4, 512, 1, true>,  cudaFuncAttributeMaxDynamicSharedMemorySize, SMEM_BYTES);

    const int nPrep = BROWS * UNITS / 4;
    prep_all_kernel<<<(nPrep + 255) / 256, 256>>>(h, x, Rm, Km);

    // N-block fastest (x), M-block slow (y): CTAs sharing A-rows are L2-concurrent.
    const dim3 gg(UNITS / 128, BROWS / 128);
    ctrnn_gemm<0, 256, 2, false><<<gg, 256, SMEM_BYTES>>>(bias, nullptr);

    for (int u = 0; u < 6; ++u) {
        ctrnn_gemm<1, 512, 1, false><<<gg, 256, SMEM_BYTES>>>(scale, nullptr);
        ctrnn_gemm<2, 512, 1, false><<<gg, 256, SMEM_BYTES>>>(scale, nullptr);
        ctrnn_gemm<3, 512, 1, false><<<gg, 256, SMEM_BYTES>>>(scale, nullptr);
        if (u == 5) ctrnn_gemm<4, 512, 1, true><<<gg, 256, SMEM_BYTES>>>(scale, out);
        else        ctrnn_gemm<4, 512, 1, false><<<gg, 256, SMEM_BYTES>>>(scale, nullptr);
    }
}

// round 13
// speedup vs baseline: 2.1848x; 2.1848x over previous
#include <cuda_runtime.h>
#include <cuda_fp16.h>
#include <cstdint>
#include <cstddef>

#define BROWS 32768
#define DIN   256
#define UNITS 512

static constexpr float DT  = 1.0f / 6.0f;
static constexpr float DT2 = DT * 0.5f;
static constexpr float DT3 = DT / 3.0f;
static constexpr float DT6 = DT / 6.0f;

// ------------------------------------------------------------------ scratch
__device__ alignas(16) float  g_XKb[(size_t)BROWS * UNITS];
__device__ alignas(16) float  g_S  [(size_t)BROWS * UNITS];
__device__ alignas(16) __half g_H0h[(size_t)BROWS * UNITS];
__device__ alignas(16) __half g_H0l[(size_t)BROWS * UNITS];
__device__ alignas(16) __half g_HAh[(size_t)BROWS * UNITS];
__device__ alignas(16) __half g_HAl[(size_t)BROWS * UNITS];
__device__ alignas(16) __half g_HBh[(size_t)BROWS * UNITS];
__device__ alignas(16) __half g_HBl[(size_t)BROWS * UNITS];
__device__ alignas(16) __half g_Xh [(size_t)BROWS * DIN];
__device__ alignas(16) __half g_Xl [(size_t)BROWS * DIN];
__device__ alignas(16) __half g_Rth[UNITS * UNITS];
__device__ alignas(16) __half g_Kth[UNITS * DIN];

// ------------------------------------------------------------------ helpers
__device__ __forceinline__ uint32_t smem_u32(const void* p) {
    uint32_t a;
    asm("{ .reg .u64 t; cvta.to.shared.u64 t, %1; cvt.u32.u64 %0, t; }" : "=r"(a) : "l"(p));
    return a;
}

__device__ __forceinline__ void cp_async16(uint32_t saddr, const void* gaddr) {
    asm volatile("cp.async.cg.shared.global [%0], [%1], 16;" :: "r"(saddr), "l"(gaddr));
}
#define CP_COMMIT() asm volatile("cp.async.commit_group;" ::: "memory")
#define CP_WAIT(n)  asm volatile("cp.async.wait_group %0;" :: "n"(n) : "memory")

__device__ __forceinline__ void pf_l2(const void* p) {
    asm volatile("prefetch.global.L2 [%0];" :: "l"(p));
}

__device__ __forceinline__ void ldsm_x4(uint32_t addr, uint32_t& r0, uint32_t& r1,
                                        uint32_t& r2, uint32_t& r3) {
    asm volatile("ldmatrix.sync.aligned.m8n8.x4.shared.b16 {%0,%1,%2,%3}, [%4];"
                 : "=r"(r0), "=r"(r1), "=r"(r2), "=r"(r3) : "r"(addr));
}

__device__ __forceinline__ void mma16816(float* c, const uint32_t* a,
                                         uint32_t b0, uint32_t b1) {
    asm volatile("mma.sync.aligned.m16n8k16.row.col.f32.f16.f16.f32 "
                 "{%0,%1,%2,%3}, {%4,%5,%6,%7}, {%8,%9}, {%0,%1,%2,%3};"
                 : "+f"(c[0]), "+f"(c[1]), "+f"(c[2]), "+f"(c[3])
                 : "r"(a[0]), "r"(a[1]), "r"(a[2]), "r"(a[3]), "r"(b0), "r"(b1));
}

__device__ __forceinline__ float tanh_fast(float x) {
    const float e = __expf(2.0f * x);
    return 1.0f - 2.0f / (e + 1.0f);
}

__device__ __forceinline__ void hsplit2(__half* ph, __half* pl, float v0, float v1) {
    const __half h0 = __float2half(v0);
    const __half h1 = __float2half(v1);
    const __half l0 = __float2half(v0 - __half2float(h0));
    const __half l1 = __float2half(v1 - __half2float(h1));
    __half2 hh; hh.x = h0; hh.y = h1;
    __half2 ll; ll.x = l0; ll.y = l1;
    *reinterpret_cast<__half2*>(ph) = hh;
    *reinterpret_cast<__half2*>(pl) = ll;
}

// ------------------------------------------------------------------ smem map (dynamic)
static constexpr uint32_t TILE_BYTES = 128 * 128;         // 128 rows x 128B (64 halfs)
static constexpr uint32_t OFF_A0  = 0;
static constexpr uint32_t OFF_A1  = OFF_A0 + TILE_BYTES;  // 16384
static constexpr uint32_t OFF_B0  = OFF_A1 + TILE_BYTES;  // 32768
static constexpr uint32_t OFF_B1  = OFF_B0 + TILE_BYTES;  // 49152
static constexpr uint32_t OFF_SCL = OFF_B1 + TILE_BYTES;  // 65536
static constexpr uint32_t SMEM_BYTES = OFF_SCL + 512 + 16;

// ------------------------------------------------------------------ main GEMM + RK4 epilogue
// 512 threads/CTA, 16 warps in a 4x4 grid, warp tile 32x32 -> 32 accs/thread.
// __launch_bounds__(512,2): 64-reg cap that FITS (unlike R11's 80-reg cap vs
// 64 accs) -> 32 warps/SM, occ ~50%, no spills. Tile/traffic/numerics
// unchanged from the 4103us baseline.
// NPASS=2: [A_hi|A_lo]@[B_hi|B_hi] (x@K). NPASS=1: A_hi@B_hi (stages).
template <int MODE, int KSEG, int NPASS, bool LAST>
__global__ void __launch_bounds__(512, 2)
ctrnn_gemm(const float* __restrict__ sb, float* __restrict__ outp) {
    extern __shared__ char smem[];
    const uint32_t sbase = smem_u32(smem);
    const int tid  = threadIdx.x;
    const int lane = tid & 31;
    const int wid  = tid >> 5;               // 0..15
    const int warpM = (wid & 3) * 32;        // 4 warps along M
    const int warpN = (wid >> 2) * 32;       // 4 warps along N
    const int rowBase = blockIdx.y * 128;
    const int nBase   = blockIdx.x * 128;

    constexpr int CHPS = KSEG / 64;
    constexpr int NCH  = NPASS * CHPS;

    const __half *Ah, *Al, *Bh;
    if constexpr (MODE == 0)      { Ah = g_Xh;  Al = g_Xl;  Bh = g_Kth; }
    else if constexpr (MODE == 1) { Ah = g_H0h; Al = g_H0l; Bh = g_Rth; }
    else if constexpr (MODE == 2) { Ah = g_HAh; Al = g_HAl; Bh = g_Rth; }
    else if constexpr (MODE == 3) { Ah = g_HBh; Al = g_HBl; Bh = g_Rth; }
    else                          { Ah = g_HAh; Al = g_HAl; Bh = g_Rth; }

    __half *nxh = nullptr, *nxl = nullptr;
    if constexpr (MODE == 1)               { nxh = g_HAh; nxl = g_HAl; }
    else if constexpr (MODE == 2)          { nxh = g_HBh; nxl = g_HBl; }
    else if constexpr (MODE == 3)          { nxh = g_HAh; nxl = g_HAl; }
    else if constexpr (MODE == 4 && !LAST) { nxh = g_H0h; nxl = g_H0l; }

    if (tid < 128)
        reinterpret_cast<float*>(smem + OFF_SCL)[tid] = sb[nBase + tid];

    const __half* Aseg[2] = {Ah, (NPASS == 2) ? Al : Ah};

    // cp.async slot map: 1024 slots per 16KB tile; 512 threads -> 2 iters each
    const int srow = tid >> 3;               // 0..63
    const int scol = tid & 7;

    auto load_chunk = [&](int c, int buf) {
        const int seg = c / CHPS;
        const int kof = (c % CHPS) * 64;
        const __half* As = Aseg[seg];
        const __half* Bs = Bh;
        const uint32_t aOff = buf ? OFF_A1 : OFF_A0;
        const uint32_t bOff = buf ? OFF_B1 : OFF_B0;
#pragma unroll
        for (int i = 0; i < 2; ++i) {
            const int r = srow + i * 64;
            uint32_t off = (uint32_t)(r * 128 + ((scol ^ (r & 7)) << 4));
            cp_async16(sbase + aOff + off,
                       As + (size_t)(rowBase + r) * KSEG + kof + scol * 8);
        }
#pragma unroll
        for (int i = 0; i < 2; ++i) {
            const int r = srow + i * 64;
            uint32_t off = (uint32_t)(r * 128 + ((scol ^ (r & 7)) << 4));
            cp_async16(sbase + bOff + off,
                       Bs + (size_t)(nBase + r) * KSEG + kof + scol * 8);
        }
        CP_COMMIT();
    };

    // L2 prefetch of epilogue operands (late; footprint fits L2)
    auto pf_f32 = [&](const float* base) {
        const int L = tid;                   // 512 lines of 128B, 1/thread
        pf_l2(base + (size_t)(rowBase + (L >> 2)) * UNITS + nBase + (L & 3) * 32);
    };
    auto pf_f16 = [&](const __half* base) {
        if (tid < 256) {
            const int L = tid;               // 256 lines, 1/thread
            pf_l2(base + (size_t)(rowBase + (L >> 1)) * UNITS + nBase + (L & 1) * 64);
        }
    };

    float acc[2][4][4];
#pragma unroll
    for (int mf = 0; mf < 2; ++mf)
#pragma unroll
        for (int nf = 0; nf < 4; ++nf)
#pragma unroll
            for (int i = 0; i < 4; ++i) acc[mf][nf][i] = 0.0f;

    // 2-stage pipeline: one barrier per chunk; L(c+1) overlaps MMA(c).
    load_chunk(0, 0);

    for (int c = 0; c < NCH; ++c) {
        CP_WAIT(0);
        __syncthreads();
        if (c + 1 < NCH) load_chunk(c + 1, (c + 1) & 1);

        if constexpr (MODE != 0) {
            if (c == NCH - 3) {
                pf_f32(g_XKb);
                pf_f16(Al);
            } else if (c == NCH - 2) {
                if constexpr (MODE >= 2) pf_f32(g_S);
                if constexpr (MODE == 2 || MODE == 3) { pf_f16(g_H0h); pf_f16(g_H0l); }
            }
        }

        const uint32_t aBase = sbase + ((c & 1) ? OFF_A1 : OFF_A0);
        const uint32_t bBase = sbase + ((c & 1) ? OFF_B1 : OFF_B0);
#pragma unroll
        for (int q = 0; q < 4; ++q) {
            uint32_t a[2][4];
#pragma unroll
            for (int mf = 0; mf < 2; ++mf) {
                const int row = warpM + mf * 16 + ((lane >> 3) & 1) * 8 + (lane & 7);
                const int c16 = q * 2 + (lane >> 4);
                const uint32_t addr = aBase + row * 128 + (((c16 ^ (row & 7)) & 7) << 4);
                ldsm_x4(addr, a[mf][0], a[mf][1], a[mf][2], a[mf][3]);
            }
#pragma unroll
            for (int g = 0; g < 2; ++g) {
                uint32_t b0, b1, b2, b3;
                const int row = warpN + g * 16 + ((lane >> 3) & 1) * 8 + (lane & 7);
                const int c16 = q * 2 + (lane >> 4);
                const uint32_t addr = bBase + row * 128 + (((c16 ^ (row & 7)) & 7) << 4);
                ldsm_x4(addr, b0, b1, b2, b3);
#pragma unroll
                for (int mf = 0; mf < 2; ++mf) {
                    mma16816(acc[mf][2 * g],     a[mf], b0, b2);
                    mma16816(acc[mf][2 * g + 1], a[mf], b1, b3);
                }
            }
        }
    }

    // ---------------- RK4 epilogue ----------------
    const float* scl = reinterpret_cast<const float*>(smem + OFF_SCL);

#pragma unroll
    for (int mf = 0; mf < 2; ++mf) {
#pragma unroll
        for (int nf = 0; nf < 4; ++nf) {
#pragma unroll
            for (int half_ = 0; half_ < 2; ++half_) {
                const int row = rowBase + warpM + mf * 16 + (lane >> 2) + half_ * 8;
                const int lc  = warpN + nf * 8 + (lane & 3) * 2;   // local col 0..127
                const int col = nBase + lc;
                const float c0 = acc[mf][nf][half_ * 2 + 0];
                const float c1 = acc[mf][nf][half_ * 2 + 1];
                const size_t eb = (size_t)row * UNITS + col;

                if constexpr (MODE == 0) {
                    float2 o;
                    o.x = c0 + scl[lc];
                    o.y = c1 + scl[lc + 1];
                    *reinterpret_cast<float2*>(g_XKb + eb) = o;
                } else {
                    const float2 xk = *reinterpret_cast<const float2*>(g_XKb + eb);
                    const __half2 ah = *reinterpret_cast<const __half2*>(Ah + eb);
                    const __half2 al = *reinterpret_cast<const __half2*>(Al + eb);
                    const float hs0 = __half2float(ah.x) + __half2float(al.x);
                    const float hs1 = __half2float(ah.y) + __half2float(al.y);
                    const float k0 = scl[lc]     * tanh_fast(c0 + xk.x) - hs0;
                    const float k1 = scl[lc + 1] * tanh_fast(c1 + xk.y) - hs1;

                    if constexpr (MODE == 1) {
                        hsplit2(nxh + eb, nxl + eb, hs0 + DT2 * k0, hs1 + DT2 * k1);
                        float2 sv; sv.x = hs0 + DT6 * k0; sv.y = hs1 + DT6 * k1;
                        *reinterpret_cast<float2*>(g_S + eb) = sv;
                    } else if constexpr (MODE == 2 || MODE == 3) {
                        const __half2 h0a = *reinterpret_cast<const __half2*>(g_H0h + eb);
                        const __half2 h0b = *reinterpret_cast<const __half2*>(g_H0l + eb);
                        const float h00 = __half2float(h0a.x) + __half2float(h0b.x);
                        const float h01 = __half2float(h0a.y) + __half2float(h0b.y);
                        const float2 s = *reinterpret_cast<const float2*>(g_S + eb);
                        constexpr float HC = (MODE == 2) ? DT2 : DT;
                        hsplit2(nxh + eb, nxl + eb, h00 + HC * k0, h01 + HC * k1);
                        float2 sn; sn.x = s.x + DT3 * k0; sn.y = s.y + DT3 * k1;
                        *reinterpret_cast<float2*>(g_S + eb) = sn;
                    } else {  // MODE 4
                        const float2 s = *reinterpret_cast<const float2*>(g_S + eb);
                        const float f0 = s.x + DT6 * k0;
                        const float f1 = s.y + DT6 * k1;
                        if constexpr (LAST) {
                            float2 o; o.x = f0; o.y = f1;
                            *reinterpret_cast<float2*>(outp + eb) = o;
                        } else {
                            hsplit2(nxh + eb, nxl + eb, f0, f1);
                        }
                    }
                }
            }
        }
    }
}

// ------------------------------------------------------------------ fused prep kernel
__global__ void prep_all_kernel(const float* __restrict__ h, const float* __restrict__ x,
                                const float* __restrict__ Rm, const float* __restrict__ Km) {
    const int i = blockIdx.x * blockDim.x + threadIdx.x;
    {
        const int nA = BROWS * UNITS / 4;
        if (i < nA) {
            const float4 v = reinterpret_cast<const float4*>(h)[i];
            hsplit2(g_H0h + (size_t)i * 4,     g_H0l + (size_t)i * 4,     v.x, v.y);
            hsplit2(g_H0h + (size_t)i * 4 + 2, g_H0l + (size_t)i * 4 + 2, v.z, v.w);
        }
    }
    {
        const int nB = BROWS * DIN / 4;
        if (i < nB) {
            const float4 v = reinterpret_cast<const float4*>(x)[i];
            hsplit2(g_Xh + (size_t)i * 4,     g_Xl + (size_t)i * 4,     v.x, v.y);
            hsplit2(g_Xh + (size_t)i * 4 + 2, g_Xl + (size_t)i * 4 + 2, v.z, v.w);
        }
    }
    {
        const int nC = UNITS * UNITS;
        if (i < nC) {
            const int k = i / UNITS, n = i % UNITS;
            g_Rth[(size_t)n * UNITS + k] = __float2half(Rm[i]);
        }
    }
    {
        const int nD = DIN * UNITS;
        if (i < nD) {
            const int k = i / UNITS, n = i % UNITS;
            g_Kth[(size_t)n * DIN + k] = __float2half(Km[i]);
        }
    }
}

// ------------------------------------------------------------------ launch
extern "C" void kernel_launch(void* const* d_in, const int* in_sizes, int n_in,
                              void* d_out, int out_size) {
    const float* x     = (const float*)d_in[0];
    const float* h     = (const float*)d_in[1];
    const float* Km    = (const float*)d_in[2];
    const float* Rm    = (const float*)d_in[3];
    const float* bias  = (const float*)d_in[4];
    const float* scale = (const float*)d_in[5];
    float* out = (float*)d_out;

    cudaFuncSetAttribute(ctrnn_gemm<0, 256, 2, false>, cudaFuncAttributeMaxDynamicSharedMemorySize, SMEM_BYTES);
    cudaFuncSetAttribute(ctrnn_gemm<1, 512, 1, false>, cudaFuncAttributeMaxDynamicSharedMemorySize, SMEM_BYTES);
    cudaFuncSetAttribute(ctrnn_gemm<2, 512, 1, false>, cudaFuncAttributeMaxDynamicSharedMemorySize, SMEM_BYTES);
    cudaFuncSetAttribute(ctrnn_gemm<3, 512, 1, false>, cudaFuncAttributeMaxDynamicSharedMemorySize, SMEM_BYTES);
    cudaFuncSetAttribute(ctrnn_gemm<4, 512, 1, false>, cudaFuncAttributeMaxDynamicSharedMemorySize, SMEM_BYTES);
    cudaFuncSetAttribute(ctrnn_gemm<4, 512, 1, true>,  cudaFuncAttributeMaxDynamicSharedMemorySize, SMEM_BYTES);

    const int nPrep = BROWS * UNITS / 4;
    prep_all_kernel<<<(nPrep + 255) / 256, 256>>>(h, x, Rm, Km);

    // N-block fastest (x), M-block slow (y): CTAs sharing A-rows are L2-concurrent.
    const dim3 gg(UNITS / 128, BROWS / 128);
    ctrnn_gemm<0, 256, 2, false><<<gg, 512, SMEM_BYTES>>>(bias, nullptr);

    for (int u = 0; u < 6; ++u) {
        ctrnn_gemm<1, 512, 1, false><<<gg, 512, SMEM_BYTES>>>(scale, nullptr);
        ctrnn_gemm<2, 512, 1, false><<<gg, 512, SMEM_BYTES>>>(scale, nullptr);
        ctrnn_gemm<3, 512, 1, false><<<gg, 512, SMEM_BYTES>>>(scale, nullptr);
        if (u == 5) ctrnn_gemm<4, 512, 1, true><<<gg, 512, SMEM_BYTES>>>(scale, out);
        else        ctrnn_gemm<4, 512, 1, false><<<gg, 512, SMEM_BYTES>>>(scale, nullptr);
    }
}

// round 14
// speedup vs baseline: 2.2640x; 1.0362x over previous
#include <cuda_runtime.h>
#include <cuda_fp16.h>
#include <cstdint>
#include <cstddef>

#define BROWS 32768
#define DIN   256
#define UNITS 512

static constexpr float DT  = 1.0f / 6.0f;
static constexpr float DT2 = DT * 0.5f;
static constexpr float DT3 = DT / 3.0f;
static constexpr float DT6 = DT / 6.0f;

// ------------------------------------------------------------------ scratch
__device__ alignas(16) __half g_XKb[(size_t)BROWS * UNITS];   // fp16: correlated bias, safe
__device__ alignas(16) float  g_S  [(size_t)BROWS * UNITS];
__device__ alignas(16) __half g_H0h[(size_t)BROWS * UNITS];
__device__ alignas(16) __half g_H0l[(size_t)BROWS * UNITS];
__device__ alignas(16) __half g_HAh[(size_t)BROWS * UNITS];
__device__ alignas(16) __half g_HAl[(size_t)BROWS * UNITS];
__device__ alignas(16) __half g_HBh[(size_t)BROWS * UNITS];
__device__ alignas(16) __half g_HBl[(size_t)BROWS * UNITS];
__device__ alignas(16) __half g_Xh [(size_t)BROWS * DIN];
__device__ alignas(16) __half g_Xl [(size_t)BROWS * DIN];
__device__ alignas(16) __half g_Rth[UNITS * UNITS];
__device__ alignas(16) __half g_Kth[UNITS * DIN];

// ------------------------------------------------------------------ helpers
__device__ __forceinline__ uint32_t smem_u32(const void* p) {
    uint32_t a;
    asm("{ .reg .u64 t; cvta.to.shared.u64 t, %1; cvt.u32.u64 %0, t; }" : "=r"(a) : "l"(p));
    return a;
}

__device__ __forceinline__ void cp_async16(uint32_t saddr, const void* gaddr) {
    asm volatile("cp.async.cg.shared.global [%0], [%1], 16;" :: "r"(saddr), "l"(gaddr));
}
#define CP_COMMIT() asm volatile("cp.async.commit_group;" ::: "memory")
#define CP_WAIT(n)  asm volatile("cp.async.wait_group %0;" :: "n"(n) : "memory")

__device__ __forceinline__ void pf_l2(const void* p) {
    asm volatile("prefetch.global.L2 [%0];" :: "l"(p));
}

__device__ __forceinline__ void ldsm_x4(uint32_t addr, uint32_t& r0, uint32_t& r1,
                                        uint32_t& r2, uint32_t& r3) {
    asm volatile("ldmatrix.sync.aligned.m8n8.x4.shared.b16 {%0,%1,%2,%3}, [%4];"
                 : "=r"(r0), "=r"(r1), "=r"(r2), "=r"(r3) : "r"(addr));
}

__device__ __forceinline__ void mma16816(float* c, const uint32_t* a,
                                         uint32_t b0, uint32_t b1) {
    asm volatile("mma.sync.aligned.m16n8k16.row.col.f32.f16.f16.f32 "
                 "{%0,%1,%2,%3}, {%4,%5,%6,%7}, {%8,%9}, {%0,%1,%2,%3};"
                 : "+f"(c[0]), "+f"(c[1]), "+f"(c[2]), "+f"(c[3])
                 : "r"(a[0]), "r"(a[1]), "r"(a[2]), "r"(a[3]), "r"(b0), "r"(b1));
}

__device__ __forceinline__ float tanh_fast(float x) {
    const float e = __expf(2.0f * x);
    return 1.0f - 2.0f / (e + 1.0f);
}

__device__ __forceinline__ void hsplit2(__half* ph, __half* pl, float v0, float v1) {
    const __half h0 = __float2half(v0);
    const __half h1 = __float2half(v1);
    const __half l0 = __float2half(v0 - __half2float(h0));
    const __half l1 = __float2half(v1 - __half2float(h1));
    __half2 hh; hh.x = h0; hh.y = h1;
    __half2 ll; ll.x = l0; ll.y = l1;
    *reinterpret_cast<__half2*>(ph) = hh;
    *reinterpret_cast<__half2*>(pl) = ll;
}

// ------------------------------------------------------------------ smem map (dynamic)
static constexpr uint32_t TILE_BYTES = 128 * 128;         // 128 rows x 128B (64 halfs)
static constexpr uint32_t OFF_A0  = 0;
static constexpr uint32_t OFF_A1  = OFF_A0 + TILE_BYTES;  // 16384
static constexpr uint32_t OFF_B0  = OFF_A1 + TILE_BYTES;  // 32768
static constexpr uint32_t OFF_B1  = OFF_B0 + TILE_BYTES;  // 49152
static constexpr uint32_t OFF_SCL = OFF_B1 + TILE_BYTES;  // 65536
static constexpr uint32_t SMEM_BYTES = OFF_SCL + 512 + 16;

// ------------------------------------------------------------------ main GEMM + RK4 epilogue
// 512 thr/CTA, 16 warps 4x4, warp tile 32x32, 32 accs -> 64 regs, 2 CTAs/SM,
// 32 warps/SM (R12 win). XKb now fp16 (read stream halved; rounding is a
// correlated bias ~3e-4 on output, inside budget).
// NPASS=1 everywhere (x_lo term < XKb rounding, so mode0 2-pass is pointless).
template <int MODE, int KSEG, int NPASS, bool LAST>
__global__ void __launch_bounds__(512, 2)
ctrnn_gemm(const float* __restrict__ sb, float* __restrict__ outp) {
    extern __shared__ char smem[];
    const uint32_t sbase = smem_u32(smem);
    const int tid  = threadIdx.x;
    const int lane = tid & 31;
    const int wid  = tid >> 5;               // 0..15
    const int warpM = (wid & 3) * 32;        // 4 warps along M
    const int warpN = (wid >> 2) * 32;       // 4 warps along N
    const int rowBase = blockIdx.y * 128;
    const int nBase   = blockIdx.x * 128;

    constexpr int CHPS = KSEG / 64;
    constexpr int NCH  = NPASS * CHPS;

    const __half *Ah, *Al, *Bh;
    if constexpr (MODE == 0)      { Ah = g_Xh;  Al = g_Xl;  Bh = g_Kth; }
    else if constexpr (MODE == 1) { Ah = g_H0h; Al = g_H0l; Bh = g_Rth; }
    else if constexpr (MODE == 2) { Ah = g_HAh; Al = g_HAl; Bh = g_Rth; }
    else if constexpr (MODE == 3) { Ah = g_HBh; Al = g_HBl; Bh = g_Rth; }
    else                          { Ah = g_HAh; Al = g_HAl; Bh = g_Rth; }

    __half *nxh = nullptr, *nxl = nullptr;
    if constexpr (MODE == 1)               { nxh = g_HAh; nxl = g_HAl; }
    else if constexpr (MODE == 2)          { nxh = g_HBh; nxl = g_HBl; }
    else if constexpr (MODE == 3)          { nxh = g_HAh; nxl = g_HAl; }
    else if constexpr (MODE == 4 && !LAST) { nxh = g_H0h; nxl = g_H0l; }

    if (tid < 128)
        reinterpret_cast<float*>(smem + OFF_SCL)[tid] = sb[nBase + tid];

    const __half* Aseg[2] = {Ah, (NPASS == 2) ? Al : Ah};

    // cp.async slot map: 1024 slots per 16KB tile; 512 threads -> 2 iters each
    const int srow = tid >> 3;               // 0..63
    const int scol = tid & 7;

    auto load_chunk = [&](int c, int buf) {
        const int seg = c / CHPS;
        const int kof = (c % CHPS) * 64;
        const __half* As = Aseg[seg];
        const __half* Bs = Bh;
        const uint32_t aOff = buf ? OFF_A1 : OFF_A0;
        const uint32_t bOff = buf ? OFF_B1 : OFF_B0;
#pragma unroll
        for (int i = 0; i < 2; ++i) {
            const int r = srow + i * 64;
            uint32_t off = (uint32_t)(r * 128 + ((scol ^ (r & 7)) << 4));
            cp_async16(sbase + aOff + off,
                       As + (size_t)(rowBase + r) * KSEG + kof + scol * 8);
        }
#pragma unroll
        for (int i = 0; i < 2; ++i) {
            const int r = srow + i * 64;
            uint32_t off = (uint32_t)(r * 128 + ((scol ^ (r & 7)) << 4));
            cp_async16(sbase + bOff + off,
                       Bs + (size_t)(nBase + r) * KSEG + kof + scol * 8);
        }
        CP_COMMIT();
    };

    // L2 prefetch of epilogue operands (late; footprint fits L2)
    auto pf_f32 = [&](const float* base) {
        const int L = tid;                   // 512 lines of 128B, 1/thread
        pf_l2(base + (size_t)(rowBase + (L >> 2)) * UNITS + nBase + (L & 3) * 32);
    };
    auto pf_f16 = [&](const __half* base) {
        if (tid < 256) {
            const int L = tid;               // 256 lines, 1/thread
            pf_l2(base + (size_t)(rowBase + (L >> 1)) * UNITS + nBase + (L & 1) * 64);
        }
    };

    float acc[2][4][4];
#pragma unroll
    for (int mf = 0; mf < 2; ++mf)
#pragma unroll
        for (int nf = 0; nf < 4; ++nf)
#pragma unroll
            for (int i = 0; i < 4; ++i) acc[mf][nf][i] = 0.0f;

    // 2-stage pipeline: one barrier per chunk; L(c+1) overlaps MMA(c).
    load_chunk(0, 0);

    for (int c = 0; c < NCH; ++c) {
        CP_WAIT(0);
        __syncthreads();
        if (c + 1 < NCH) load_chunk(c + 1, (c + 1) & 1);

        if constexpr (MODE != 0) {
            if (c == NCH - 3) {
                pf_f16(g_XKb);
                pf_f16(Al);
            } else if (c == NCH - 2) {
                if constexpr (MODE >= 2) pf_f32(g_S);
                if constexpr (MODE == 2 || MODE == 3) { pf_f16(g_H0h); pf_f16(g_H0l); }
            }
        }

        const uint32_t aBase = sbase + ((c & 1) ? OFF_A1 : OFF_A0);
        const uint32_t bBase = sbase + ((c & 1) ? OFF_B1 : OFF_B0);
#pragma unroll
        for (int q = 0; q < 4; ++q) {
            uint32_t a[2][4];
#pragma unroll
            for (int mf = 0; mf < 2; ++mf) {
                const int row = warpM + mf * 16 + ((lane >> 3) & 1) * 8 + (lane & 7);
                const int c16 = q * 2 + (lane >> 4);
                const uint32_t addr = aBase + row * 128 + (((c16 ^ (row & 7)) & 7) << 4);
                ldsm_x4(addr, a[mf][0], a[mf][1], a[mf][2], a[mf][3]);
            }
#pragma unroll
            for (int g = 0; g < 2; ++g) {
                uint32_t b0, b1, b2, b3;
                const int row = warpN + g * 16 + ((lane >> 3) & 1) * 8 + (lane & 7);
                const int c16 = q * 2 + (lane >> 4);
                const uint32_t addr = bBase + row * 128 + (((c16 ^ (row & 7)) & 7) << 4);
                ldsm_x4(addr, b0, b1, b2, b3);
#pragma unroll
                for (int mf = 0; mf < 2; ++mf) {
                    mma16816(acc[mf][2 * g],     a[mf], b0, b2);
                    mma16816(acc[mf][2 * g + 1], a[mf], b1, b3);
                }
            }
        }
    }

    // ---------------- RK4 epilogue ----------------
    const float* scl = reinterpret_cast<const float*>(smem + OFF_SCL);

#pragma unroll
    for (int mf = 0; mf < 2; ++mf) {
#pragma unroll
        for (int nf = 0; nf < 4; ++nf) {
#pragma unroll
            for (int half_ = 0; half_ < 2; ++half_) {
                const int row = rowBase + warpM + mf * 16 + (lane >> 2) + half_ * 8;
                const int lc  = warpN + nf * 8 + (lane & 3) * 2;   // local col 0..127
                const int col = nBase + lc;
                const float c0 = acc[mf][nf][half_ * 2 + 0];
                const float c1 = acc[mf][nf][half_ * 2 + 1];
                const size_t eb = (size_t)row * UNITS + col;

                if constexpr (MODE == 0) {
                    const __half2 o = __floats2half2_rn(c0 + scl[lc], c1 + scl[lc + 1]);
                    *reinterpret_cast<__half2*>(g_XKb + eb) = o;
                } else {
                    const __half2 xk2 = *reinterpret_cast<const __half2*>(g_XKb + eb);
                    const float xkx = __half2float(xk2.x);
                    const float xky = __half2float(xk2.y);
                    const __half2 ah = *reinterpret_cast<const __half2*>(Ah + eb);
                    const __half2 al = *reinterpret_cast<const __half2*>(Al + eb);
                    const float hs0 = __half2float(ah.x) + __half2float(al.x);
                    const float hs1 = __half2float(ah.y) + __half2float(al.y);
                    const float k0 = scl[lc]     * tanh_fast(c0 + xkx) - hs0;
                    const float k1 = scl[lc + 1] * tanh_fast(c1 + xky) - hs1;

                    if constexpr (MODE == 1) {
                        hsplit2(nxh + eb, nxl + eb, hs0 + DT2 * k0, hs1 + DT2 * k1);
                        float2 sv; sv.x = hs0 + DT6 * k0; sv.y = hs1 + DT6 * k1;
                        *reinterpret_cast<float2*>(g_S + eb) = sv;
                    } else if constexpr (MODE == 2 || MODE == 3) {
                        const __half2 h0a = *reinterpret_cast<const __half2*>(g_H0h + eb);
                        const __half2 h0b = *reinterpret_cast<const __half2*>(g_H0l + eb);
                        const float h00 = __half2float(h0a.x) + __half2float(h0b.x);
                        const float h01 = __half2float(h0a.y) + __half2float(h0b.y);
                        const float2 s = *reinterpret_cast<const float2*>(g_S + eb);
                        constexpr float HC = (MODE == 2) ? DT2 : DT;
                        hsplit2(nxh + eb, nxl + eb, h00 + HC * k0, h01 + HC * k1);
                        float2 sn; sn.x = s.x + DT3 * k0; sn.y = s.y + DT3 * k1;
                        *reinterpret_cast<float2*>(g_S + eb) = sn;
                    } else {  // MODE 4
                        const float2 s = *reinterpret_cast<const float2*>(g_S + eb);
                        const float f0 = s.x + DT6 * k0;
                        const float f1 = s.y + DT6 * k1;
                        if constexpr (LAST) {
                            float2 o; o.x = f0; o.y = f1;
                            *reinterpret_cast<float2*>(outp + eb) = o;
                        } else {
                            hsplit2(nxh + eb, nxl + eb, f0, f1);
                        }
                    }
                }
            }
        }
    }
}

// ------------------------------------------------------------------ fused prep kernel
__global__ void prep_all_kernel(const float* __restrict__ h, const float* __restrict__ x,
                                const float* __restrict__ Rm, const float* __restrict__ Km) {
    const int i = blockIdx.x * blockDim.x + threadIdx.x;
    {
        const int nA = BROWS * UNITS / 4;
        if (i < nA) {
            const float4 v = reinterpret_cast<const float4*>(h)[i];
            hsplit2(g_H0h + (size_t)i * 4,     g_H0l + (size_t)i * 4,     v.x, v.y);
            hsplit2(g_H0h + (size_t)i * 4 + 2, g_H0l + (size_t)i * 4 + 2, v.z, v.w);
        }
    }
    {
        const int nB = BROWS * DIN / 4;
        if (i < nB) {
            const float4 v = reinterpret_cast<const float4*>(x)[i];
            hsplit2(g_Xh + (size_t)i * 4,     g_Xl + (size_t)i * 4,     v.x, v.y);
            hsplit2(g_Xh + (size_t)i * 4 + 2, g_Xl + (size_t)i * 4 + 2, v.z, v.w);
        }
    }
    {
        const int nC = UNITS * UNITS;
        if (i < nC) {
            const int k = i / UNITS, n = i % UNITS;
            g_Rth[(size_t)n * UNITS + k] = __float2half(Rm[i]);
        }
    }
    {
        const int nD = DIN * UNITS;
        if (i < nD) {
            const int k = i / UNITS, n = i % UNITS;
            g_Kth[(size_t)n * DIN + k] = __float2half(Km[i]);
        }
    }
}

// ------------------------------------------------------------------ launch
extern "C" void kernel_launch(void* const* d_in, const int* in_sizes, int n_in,
                              void* d_out, int out_size) {
    const float* x     = (const float*)d_in[0];
    const float* h     = (const float*)d_in[1];
    const float* Km    = (const float*)d_in[2];
    const float* Rm    = (const float*)d_in[3];
    const float* bias  = (const float*)d_in[4];
    const float* scale = (const float*)d_in[5];
    float* out = (float*)d_out;

    cudaFuncSetAttribute(ctrnn_gemm<0, 256, 1, false>, cudaFuncAttributeMaxDynamicSharedMemorySize, SMEM_BYTES);
    cudaFuncSetAttribute(ctrnn_gemm<1, 512, 1, false>, cudaFuncAttributeMaxDynamicSharedMemorySize, SMEM_BYTES);
    cudaFuncSetAttribute(ctrnn_gemm<2, 512, 1, false>, cudaFuncAttributeMaxDynamicSharedMemorySize, SMEM_BYTES);
    cudaFuncSetAttribute(ctrnn_gemm<3, 512, 1, false>, cudaFuncAttributeMaxDynamicSharedMemorySize, SMEM_BYTES);
    cudaFuncSetAttribute(ctrnn_gemm<4, 512, 1, false>, cudaFuncAttributeMaxDynamicSharedMemorySize, SMEM_BYTES);
    cudaFuncSetAttribute(ctrnn_gemm<4, 512, 1, true>,  cudaFuncAttributeMaxDynamicSharedMemorySize, SMEM_BYTES);

    const int nPrep = BROWS * UNITS / 4;
    prep_all_kernel<<<(nPrep + 255) / 256, 256>>>(h, x, Rm, Km);

    // N-block fastest (x), M-block slow (y): CTAs sharing A-rows are L2-concurrent.
    const dim3 gg(UNITS / 128, BROWS / 128);
    ctrnn_gemm<0, 256, 1, false><<<gg, 512, SMEM_BYTES>>>(bias, nullptr);

    for (int u = 0; u < 6; ++u) {
        ctrnn_gemm<1, 512, 1, false><<<gg, 512, SMEM_BYTES>>>(scale, nullptr);
        ctrnn_gemm<2, 512, 1, false><<<gg, 512, SMEM_BYTES>>>(scale, nullptr);
        ctrnn_gemm<3, 512, 1, false><<<gg, 512, SMEM_BYTES>>>(scale, nullptr);
        if (u == 5) ctrnn_gemm<4, 512, 1, true><<<gg, 512, SMEM_BYTES>>>(scale, out);
        else        ctrnn_gemm<4, 512, 1, false><<<gg, 512, SMEM_BYTES>>>(scale, nullptr);
    }
}

// round 15
// speedup vs baseline: 2.5886x; 1.1434x over previous
#include <cuda_runtime.h>
#include <cuda_fp16.h>
#include <cstdint>
#include <cstddef>

#define BROWS 32768
#define DIN   256
#define UNITS 512

static constexpr float DT  = 1.0f / 6.0f;
static constexpr float DT2 = DT * 0.5f;
static constexpr float DT3 = DT / 3.0f;
static constexpr float DT6 = DT / 6.0f;

// ------------------------------------------------------------------ scratch
__device__ alignas(16) __half g_XKb[(size_t)BROWS * UNITS];
__device__ alignas(16) float  g_S  [(size_t)BROWS * UNITS];
__device__ alignas(16) __half g_H0h[(size_t)BROWS * UNITS];
__device__ alignas(16) __half g_H0l[(size_t)BROWS * UNITS];
__device__ alignas(16) __half g_HAh[(size_t)BROWS * UNITS];
__device__ alignas(16) __half g_HAl[(size_t)BROWS * UNITS];
__device__ alignas(16) __half g_HBh[(size_t)BROWS * UNITS];
__device__ alignas(16) __half g_HBl[(size_t)BROWS * UNITS];
__device__ alignas(16) __half g_Xh [(size_t)BROWS * DIN];
__device__ alignas(16) __half g_Xl [(size_t)BROWS * DIN];
__device__ alignas(16) __half g_Rth[UNITS * UNITS];
__device__ alignas(16) __half g_Kth[UNITS * DIN];

// ------------------------------------------------------------------ helpers
__device__ __forceinline__ uint32_t smem_u32(const void* p) {
    uint32_t a;
    asm("{ .reg .u64 t; cvta.to.shared.u64 t, %1; cvt.u32.u64 %0, t; }" : "=r"(a) : "l"(p));
    return a;
}

__device__ __forceinline__ void cp_async16(uint32_t saddr, const void* gaddr) {
    asm volatile("cp.async.cg.shared.global [%0], [%1], 16;" :: "r"(saddr), "l"(gaddr));
}
#define CP_COMMIT() asm volatile("cp.async.commit_group;" ::: "memory")
#define CP_WAIT(n)  asm volatile("cp.async.wait_group %0;" :: "n"(n) : "memory")

__device__ __forceinline__ void pf_l2(const void* p) {
    asm volatile("prefetch.global.L2 [%0];" :: "l"(p));
}

__device__ __forceinline__ void ldsm_x4(uint32_t addr, uint32_t& r0, uint32_t& r1,
                                        uint32_t& r2, uint32_t& r3) {
    asm volatile("ldmatrix.sync.aligned.m8n8.x4.shared.b16 {%0,%1,%2,%3}, [%4];"
                 : "=r"(r0), "=r"(r1), "=r"(r2), "=r"(r3) : "r"(addr));
}

__device__ __forceinline__ void mma16816(float* c, const uint32_t* a,
                                         uint32_t b0, uint32_t b1) {
    asm volatile("mma.sync.aligned.m16n8k16.row.col.f32.f16.f16.f32 "
                 "{%0,%1,%2,%3}, {%4,%5,%6,%7}, {%8,%9}, {%0,%1,%2,%3};"
                 : "+f"(c[0]), "+f"(c[1]), "+f"(c[2]), "+f"(c[3])
                 : "r"(a[0]), "r"(a[1]), "r"(a[2]), "r"(a[3]), "r"(b0), "r"(b1));
}

__device__ __forceinline__ float tanh_fast(float x) {
    const float e = __expf(2.0f * x);
    return 1.0f - 2.0f / (e + 1.0f);
}

__device__ __forceinline__ void hsplit2(__half* ph, __half* pl, float v0, float v1) {
    const __half h0 = __float2half(v0);
    const __half h1 = __float2half(v1);
    const __half l0 = __float2half(v0 - __half2float(h0));
    const __half l1 = __float2half(v1 - __half2float(h1));
    __half2 hh; hh.x = h0; hh.y = h1;
    __half2 ll; ll.x = l0; ll.y = l1;
    *reinterpret_cast<__half2*>(ph) = hh;
    *reinterpret_cast<__half2*>(pl) = ll;
}

// ------------------------------------------------------------------ smem map (dynamic)
static constexpr uint32_t TILE_BYTES = 128 * 128;
static constexpr uint32_t OFF_A0  = 0;
static constexpr uint32_t OFF_A1  = OFF_A0 + TILE_BYTES;
static constexpr uint32_t OFF_B0  = OFF_A1 + TILE_BYTES;
static constexpr uint32_t OFF_B1  = OFF_B0 + TILE_BYTES;
static constexpr uint32_t OFF_SCL = OFF_B1 + TILE_BYTES;  // 65536
static constexpr uint32_t SMEM_BYTES = OFF_SCL + 512 + 16;

// epilogue scratch: 64 rows x 528B (132 floats, padded vs bank conflicts)
// fits in the 64KB of dead mainloop buffers (OFF_A0..OFF_SCL)
static constexpr uint32_t EPI_ROW_B = 528;

// ------------------------------------------------------------------ main GEMM + RK4 epilogue
template <int MODE, int KSEG, int NPASS, bool LAST>
__global__ void __launch_bounds__(512, 2)
ctrnn_gemm(const float* __restrict__ sb, float* __restrict__ outp) {
    extern __shared__ char smem[];
    const uint32_t sbase = smem_u32(smem);
    const int tid  = threadIdx.x;
    const int lane = tid & 31;
    const int wid  = tid >> 5;
    const int warpM = (wid & 3) * 32;
    const int warpN = (wid >> 2) * 32;
    const int rowBase = blockIdx.y * 128;
    const int nBase   = blockIdx.x * 128;

    constexpr int CHPS = KSEG / 64;
    constexpr int NCH  = NPASS * CHPS;

    const __half *Ah, *Al, *Bh;
    if constexpr (MODE == 0)      { Ah = g_Xh;  Al = g_Xl;  Bh = g_Kth; }
    else if constexpr (MODE == 1) { Ah = g_H0h; Al = g_H0l; Bh = g_Rth; }
    else if constexpr (MODE == 2) { Ah = g_HAh; Al = g_HAl; Bh = g_Rth; }
    else if constexpr (MODE == 3) { Ah = g_HBh; Al = g_HBl; Bh = g_Rth; }
    else                          { Ah = g_HAh; Al = g_HAl; Bh = g_Rth; }

    __half *nxh = nullptr, *nxl = nullptr;
    if constexpr (MODE == 1)               { nxh = g_HAh; nxl = g_HAl; }
    else if constexpr (MODE == 2)          { nxh = g_HBh; nxl = g_HBl; }
    else if constexpr (MODE == 3)          { nxh = g_HAh; nxl = g_HAl; }
    else if constexpr (MODE == 4 && !LAST) { nxh = g_H0h; nxl = g_H0l; }

    if (tid < 128)
        reinterpret_cast<float*>(smem + OFF_SCL)[tid] = sb[nBase + tid];

    const __half* Aseg[2] = {Ah, (NPASS == 2) ? Al : Ah};

    const int srow = tid >> 3;
    const int scol = tid & 7;

    auto load_chunk = [&](int c, int buf) {
        const int seg = c / CHPS;
        const int kof = (c % CHPS) * 64;
        const __half* As = Aseg[seg];
        const __half* Bs = Bh;
        const uint32_t aOff = buf ? OFF_A1 : OFF_A0;
        const uint32_t bOff = buf ? OFF_B1 : OFF_B0;
#pragma unroll
        for (int i = 0; i < 2; ++i) {
            const int r = srow + i * 64;
            uint32_t off = (uint32_t)(r * 128 + ((scol ^ (r & 7)) << 4));
            cp_async16(sbase + aOff + off,
                       As + (size_t)(rowBase + r) * KSEG + kof + scol * 8);
        }
#pragma unroll
        for (int i = 0; i < 2; ++i) {
            const int r = srow + i * 64;
            uint32_t off = (uint32_t)(r * 128 + ((scol ^ (r & 7)) << 4));
            cp_async16(sbase + bOff + off,
                       Bs + (size_t)(nBase + r) * KSEG + kof + scol * 8);
        }
        CP_COMMIT();
    };

    auto pf_f32 = [&](const float* base) {
        const int L = tid;
        pf_l2(base + (size_t)(rowBase + (L >> 2)) * UNITS + nBase + (L & 3) * 32);
    };
    auto pf_f16 = [&](const __half* base) {
        if (tid < 256) {
            const int L = tid;
            pf_l2(base + (size_t)(rowBase + (L >> 1)) * UNITS + nBase + (L & 1) * 64);
        }
    };

    float acc[2][4][4];
#pragma unroll
    for (int mf = 0; mf < 2; ++mf)
#pragma unroll
        for (int nf = 0; nf < 4; ++nf)
#pragma unroll
            for (int i = 0; i < 4; ++i) acc[mf][nf][i] = 0.0f;

    load_chunk(0, 0);

    for (int c = 0; c < NCH; ++c) {
        CP_WAIT(0);
        __syncthreads();
        if (c + 1 < NCH) load_chunk(c + 1, (c + 1) & 1);

        if constexpr (MODE != 0) {
            if (c == NCH - 3) {
                pf_f16(g_XKb);
                pf_f16(Al);
            } else if (c == NCH - 2) {
                if constexpr (MODE >= 2) pf_f32(g_S);
                if constexpr (MODE == 2 || MODE == 3) { pf_f16(g_H0h); pf_f16(g_H0l); }
            }
        }

        const uint32_t aBase = sbase + ((c & 1) ? OFF_A1 : OFF_A0);
        const uint32_t bBase = sbase + ((c & 1) ? OFF_B1 : OFF_B0);
#pragma unroll
        for (int q = 0; q < 4; ++q) {
            uint32_t a[2][4];
#pragma unroll
            for (int mf = 0; mf < 2; ++mf) {
                const int row = warpM + mf * 16 + ((lane >> 3) & 1) * 8 + (lane & 7);
                const int c16 = q * 2 + (lane >> 4);
                const uint32_t addr = aBase + row * 128 + (((c16 ^ (row & 7)) & 7) << 4);
                ldsm_x4(addr, a[mf][0], a[mf][1], a[mf][2], a[mf][3]);
            }
#pragma unroll
            for (int g = 0; g < 2; ++g) {
                uint32_t b0, b1, b2, b3;
                const int row = warpN + g * 16 + ((lane >> 3) & 1) * 8 + (lane & 7);
                const int c16 = q * 2 + (lane >> 4);
                const uint32_t addr = bBase + row * 128 + (((c16 ^ (row & 7)) & 7) << 4);
                ldsm_x4(addr, b0, b1, b2, b3);
#pragma unroll
                for (int mf = 0; mf < 2; ++mf) {
                    mma16816(acc[mf][2 * g],     a[mf], b0, b2);
                    mma16816(acc[mf][2 * g + 1], a[mf], b1, b3);
                }
            }
        }
    }

    const float* scl = reinterpret_cast<const float*>(smem + OFF_SCL);

    if constexpr (MODE == 0) {
        // x@K runs once: keep the simple scattered epilogue
#pragma unroll
        for (int mf = 0; mf < 2; ++mf)
#pragma unroll
            for (int nf = 0; nf < 4; ++nf)
#pragma unroll
                for (int hf = 0; hf < 2; ++hf) {
                    const int row = rowBase + warpM + mf * 16 + (lane >> 2) + hf * 8;
                    const int lc  = warpN + nf * 8 + (lane & 3) * 2;
                    const size_t eb = (size_t)row * UNITS + nBase + lc;
                    const __half2 o = __floats2half2_rn(acc[mf][nf][hf * 2] + scl[lc],
                                                        acc[mf][nf][hf * 2 + 1] + scl[lc + 1]);
                    *reinterpret_cast<__half2*>(g_XKb + eb) = o;
                }
    } else {
        // ---- SMEM-staged coalesced epilogue: two 64-row passes ----
#pragma unroll
        for (int p = 0; p < 2; ++p) {
            __syncthreads();      // scratch free (mainloop / prev pass done)
            if (((wid & 3) >> 1) == p) {
                const int rb = warpM - p * 64;   // 0 or 32
#pragma unroll
                for (int mf = 0; mf < 2; ++mf)
#pragma unroll
                    for (int nf = 0; nf < 4; ++nf)
#pragma unroll
                        for (int hf = 0; hf < 2; ++hf) {
                            const int rloc = rb + mf * 16 + (lane >> 2) + hf * 8;
                            const int lc   = warpN + nf * 8 + (lane & 3) * 2;
                            float2 v;
                            v.x = acc[mf][nf][hf * 2];
                            v.y = acc[mf][nf][hf * 2 + 1];
                            *reinterpret_cast<float2*>(smem + rloc * EPI_ROW_B + lc * 4) = v;
                        }
            }
            __syncthreads();

            const int r   = tid >> 3;            // 0..63
            const int seg = tid & 7;             // 0..7 -> 16 cols each
            const int grow = rowBase + p * 64 + r;
            const int lc0  = seg * 16;
            const size_t ebase = (size_t)grow * UNITS + nBase + lc0;

#pragma unroll
            for (int j = 0; j < 2; ++j) {        // 8 cols per group
                const int lcj = lc0 + j * 8;
                const size_t eb = ebase + j * 8;

                float pre[8];
#pragma unroll
                for (int i = 0; i < 2; ++i) {
                    const float4 v = *reinterpret_cast<const float4*>(
                        smem + r * EPI_ROW_B + (lcj + i * 4) * 4);
                    pre[i * 4 + 0] = v.x; pre[i * 4 + 1] = v.y;
                    pre[i * 4 + 2] = v.z; pre[i * 4 + 3] = v.w;
                }
                __half xk[8], ahv[8], alv[8];
                *reinterpret_cast<uint4*>(xk)  = *reinterpret_cast<const uint4*>(g_XKb + eb);
                *reinterpret_cast<uint4*>(ahv) = *reinterpret_cast<const uint4*>(Ah + eb);
                *reinterpret_cast<uint4*>(alv) = *reinterpret_cast<const uint4*>(Al + eb);

                float hs[8], k[8];
#pragma unroll
                for (int i = 0; i < 8; ++i) {
                    hs[i] = __half2float(ahv[i]) + __half2float(alv[i]);
                    k[i] = scl[lcj + i] * tanh_fast(pre[i] + __half2float(xk[i])) - hs[i];
                }

                if constexpr (MODE == 1) {
                    __half hh[8], hl[8];
                    float sv[8];
#pragma unroll
                    for (int i = 0; i < 8; ++i) {
                        const float hn = hs[i] + DT2 * k[i];
                        hh[i] = __float2half(hn);
                        hl[i] = __float2half(hn - __half2float(hh[i]));
                        sv[i] = hs[i] + DT6 * k[i];
                    }
                    *reinterpret_cast<uint4*>(nxh + eb) = *reinterpret_cast<uint4*>(hh);
                    *reinterpret_cast<uint4*>(nxl + eb) = *reinterpret_cast<uint4*>(hl);
                    *reinterpret_cast<float4*>(g_S + eb)     = make_float4(sv[0], sv[1], sv[2], sv[3]);
                    *reinterpret_cast<float4*>(g_S + eb + 4) = make_float4(sv[4], sv[5], sv[6], sv[7]);
                } else if constexpr (MODE == 2 || MODE == 3) {
                    __half h0h[8], h0l[8];
                    *reinterpret_cast<uint4*>(h0h) = *reinterpret_cast<const uint4*>(g_H0h + eb);
                    *reinterpret_cast<uint4*>(h0l) = *reinterpret_cast<const uint4*>(g_H0l + eb);
                    float sv[8];
                    {
                        const float4 s0 = *reinterpret_cast<const float4*>(g_S + eb);
                        const float4 s1 = *reinterpret_cast<const float4*>(g_S + eb + 4);
                        sv[0] = s0.x; sv[1] = s0.y; sv[2] = s0.z; sv[3] = s0.w;
                        sv[4] = s1.x; sv[5] = s1.y; sv[6] = s1.z; sv[7] = s1.w;
                    }
                    constexpr float HC = (MODE == 2) ? DT2 : DT;
                    __half hh[8], hl[8];
#pragma unroll
                    for (int i = 0; i < 8; ++i) {
                        const float h0v = __half2float(h0h[i]) + __half2float(h0l[i]);
                        const float hn = h0v + HC * k[i];
                        hh[i] = __float2half(hn);
                        hl[i] = __float2half(hn - __half2float(hh[i]));
                        sv[i] += DT3 * k[i];
                    }
                    *reinterpret_cast<uint4*>(nxh + eb) = *reinterpret_cast<uint4*>(hh);
                    *reinterpret_cast<uint4*>(nxl + eb) = *reinterpret_cast<uint4*>(hl);
                    *reinterpret_cast<float4*>(g_S + eb)     = make_float4(sv[0], sv[1], sv[2], sv[3]);
                    *reinterpret_cast<float4*>(g_S + eb + 4) = make_float4(sv[4], sv[5], sv[6], sv[7]);
                } else {  // MODE 4
                    float fv[8];
                    {
                        const float4 s0 = *reinterpret_cast<const float4*>(g_S + eb);
                        const float4 s1 = *reinterpret_cast<const float4*>(g_S + eb + 4);
                        fv[0] = s0.x + DT6 * k[0]; fv[1] = s0.y + DT6 * k[1];
                        fv[2] = s0.z + DT6 * k[2]; fv[3] = s0.w + DT6 * k[3];
                        fv[4] = s1.x + DT6 * k[4]; fv[5] = s1.y + DT6 * k[5];
                        fv[6] = s1.z + DT6 * k[6]; fv[7] = s1.w + DT6 * k[7];
                    }
                    if constexpr (LAST) {
                        *reinterpret_cast<float4*>(outp + eb)     = make_float4(fv[0], fv[1], fv[2], fv[3]);
                        *reinterpret_cast<float4*>(outp + eb + 4) = make_float4(fv[4], fv[5], fv[6], fv[7]);
                    } else {
                        __half hh[8], hl[8];
#pragma unroll
                        for (int i = 0; i < 8; ++i) {
                            hh[i] = __float2half(fv[i]);
                            hl[i] = __float2half(fv[i] - __half2float(hh[i]));
                        }
                        *reinterpret_cast<uint4*>(nxh + eb) = *reinterpret_cast<uint4*>(hh);
                        *reinterpret_cast<uint4*>(nxl + eb) = *reinterpret_cast<uint4*>(hl);
                    }
                }
            }
        }
    }
}

// ------------------------------------------------------------------ fused prep kernel
__global__ void prep_all_kernel(const float* __restrict__ h, const float* __restrict__ x,
                                const float* __restrict__ Rm, const float* __restrict__ Km) {
    const int i = blockIdx.x * blockDim.x + threadIdx.x;
    {
        const int nA = BROWS * UNITS / 4;
        if (i < nA) {
            const float4 v = reinterpret_cast<const float4*>(h)[i];
            hsplit2(g_H0h + (size_t)i * 4,     g_H0l + (size_t)i * 4,     v.x, v.y);
            hsplit2(g_H0h + (size_t)i * 4 + 2, g_H0l + (size_t)i * 4 + 2, v.z, v.w);
        }
    }
    {
        const int nB = BROWS * DIN / 4;
        if (i < nB) {
            const float4 v = reinterpret_cast<const float4*>(x)[i];
            hsplit2(g_Xh + (size_t)i * 4,     g_Xl + (size_t)i * 4,     v.x, v.y);
            hsplit2(g_Xh + (size_t)i * 4 + 2, g_Xl + (size_t)i * 4 + 2, v.z, v.w);
        }
    }
    {
        const int nC = UNITS * UNITS;
        if (i < nC) {
            const int k = i / UNITS, n = i % UNITS;
            g_Rth[(size_t)n * UNITS + k] = __float2half(Rm[i]);
        }
    }
    {
        const int nD = DIN * UNITS;
        if (i < nD) {
            const int k = i / UNITS, n = i % UNITS;
            g_Kth[(size_t)n * DIN + k] = __float2half(Km[i]);
        }
    }
}

// ------------------------------------------------------------------ launch
extern "C" void kernel_launch(void* const* d_in, const int* in_sizes, int n_in,
                              void* d_out, int out_size) {
    const float* x     = (const float*)d_in[0];
    const float* h     = (const float*)d_in[1];
    const float* Km    = (const float*)d_in[2];
    const float* Rm    = (const float*)d_in[3];
    const float* bias  = (const float*)d_in[4];
    const float* scale = (const float*)d_in[5];
    float* out = (float*)d_out;

    cudaFuncSetAttribute(ctrnn_gemm<0, 256, 1, false>, cudaFuncAttributeMaxDynamicSharedMemorySize, SMEM_BYTES);
    cudaFuncSetAttribute(ctrnn_gemm<1, 512, 1, false>, cudaFuncAttributeMaxDynamicSharedMemorySize, SMEM_BYTES);
    cudaFuncSetAttribute(ctrnn_gemm<2, 512, 1, false>, cudaFuncAttributeMaxDynamicSharedMemorySize, SMEM_BYTES);
    cudaFuncSetAttribute(ctrnn_gemm<3, 512, 1, false>, cudaFuncAttributeMaxDynamicSharedMemorySize, SMEM_BYTES);
    cudaFuncSetAttribute(ctrnn_gemm<4, 512, 1, false>, cudaFuncAttributeMaxDynamicSharedMemorySize, SMEM_BYTES);
    cudaFuncSetAttribute(ctrnn_gemm<4, 512, 1, true>,  cudaFuncAttributeMaxDynamicSharedMemorySize, SMEM_BYTES);

    const int nPrep = BROWS * UNITS / 4;
    prep_all_kernel<<<(nPrep + 255) / 256, 256>>>(h, x, Rm, Km);

    const dim3 gg(UNITS / 128, BROWS / 128);
    ctrnn_gemm<0, 256, 1, false><<<gg, 512, SMEM_BYTES>>>(bias, nullptr);

    for (int u = 0; u < 6; ++u) {
        ctrnn_gemm<1, 512, 1, false><<<gg, 512, SMEM_BYTES>>>(scale, nullptr);
        ctrnn_gemm<2, 512, 1, false><<<gg, 512, SMEM_BYTES>>>(scale, nullptr);
        ctrnn_gemm<3, 512, 1, false><<<gg, 512, SMEM_BYTES>>>(scale, nullptr);
        if (u == 5) ctrnn_gemm<4, 512, 1, true><<<gg, 512, SMEM_BYTES>>>(scale, out);
        else        ctrnn_gemm<4, 512, 1, false><<<gg, 512, SMEM_BYTES>>>(scale, nullptr);
    }
}

// round 16
// speedup vs baseline: 2.6213x; 1.0126x over previous
#include <cuda_runtime.h>
#include <cuda_fp16.h>
#include <cstdint>
#include <cstddef>

#define BROWS 32768
#define DIN   256
#define UNITS 512

static constexpr float DT  = 1.0f / 6.0f;
static constexpr float DT2 = DT * 0.5f;
static constexpr float DT3 = DT / 3.0f;
static constexpr float DT6 = DT / 6.0f;

__device__ alignas(16) __half g_XKb[(size_t)BROWS * UNITS];
__device__ alignas(16) float  g_S  [(size_t)BROWS * UNITS];
__device__ alignas(16) __half g_H0h[(size_t)BROWS * UNITS];
__device__ alignas(16) __half g_H0l[(size_t)BROWS * UNITS];
__device__ alignas(16) __half g_HAh[(size_t)BROWS * UNITS];
__device__ alignas(16) __half g_HAl[(size_t)BROWS * UNITS];
__device__ alignas(16) __half g_HBh[(size_t)BROWS * UNITS];
__device__ alignas(16) __half g_HBl[(size_t)BROWS * UNITS];
__device__ alignas(16) __half g_Xh [(size_t)BROWS * DIN];
__device__ alignas(16) __half g_Xl [(size_t)BROWS * DIN];
__device__ alignas(16) __half g_Rth[UNITS * UNITS];
__device__ alignas(16) __half g_Kth[UNITS * DIN];
__device__ int g_flag[BROWS / 128];

__device__ __forceinline__ uint32_t smem_u32(const void* p) {
    uint32_t a;
    asm("{ .reg .u64 t; cvta.to.shared.u64 t, %1; cvt.u32.u64 %0, t; }" : "=r"(a) : "l"(p));
    return a;
}
__device__ __forceinline__ void cp_async16(uint32_t saddr, const void* gaddr) {
    asm volatile("cp.async.cg.shared.global [%0], [%1], 16;" :: "r"(saddr), "l"(gaddr));
}
#define CP_COMMIT() asm volatile("cp.async.commit_group;" ::: "memory")
#define CP_WAIT(n)  asm volatile("cp.async.wait_group %0;" :: "n"(n) : "memory")
__device__ __forceinline__ void pf_l2(const void* p) {
    asm volatile("prefetch.global.L2 [%0];" :: "l"(p));
}
__device__ __forceinline__ void ldsm_x4(uint32_t addr, uint32_t& r0, uint32_t& r1,
                                        uint32_t& r2, uint32_t& r3) {
    asm volatile("ldmatrix.sync.aligned.m8n8.x4.shared.b16 {%0,%1,%2,%3}, [%4];"
                 : "=r"(r0), "=r"(r1), "=r"(r2), "=r"(r3) : "r"(addr));
}
__device__ __forceinline__ void mma16816(float* c, const uint32_t* a,
                                         uint32_t b0, uint32_t b1) {
    asm volatile("mma.sync.aligned.m16n8k16.row.col.f32.f16.f16.f32 "
                 "{%0,%1,%2,%3}, {%4,%5,%6,%7}, {%8,%9}, {%0,%1,%2,%3};"
                 : "+f"(c[0]), "+f"(c[1]), "+f"(c[2]), "+f"(c[3])
                 : "r"(a[0]), "r"(a[1]), "r"(a[2]), "r"(a[3]), "r"(b0), "r"(b1));
}
__device__ __forceinline__ float tanh_fast(float x) {
    const float e = __expf(2.0f * x);
    return 1.0f - 2.0f / (e + 1.0f);
}
__device__ __forceinline__ void hsplit2(__half* ph, __half* pl, float v0, float v1) {
    const __half h0 = __float2half(v0);
    const __half h1 = __float2half(v1);
    const __half l0 = __float2half(v0 - __half2float(h0));
    const __half l1 = __float2half(v1 - __half2float(h1));
    __half2 hh; hh.x = h0; hh.y = h1;
    __half2 ll; ll.x = l0; ll.y = l1;
    *reinterpret_cast<__half2*>(ph) = hh;
    *reinterpret_cast<__half2*>(pl) = ll;
}

static constexpr uint32_t TILE_BYTES = 128 * 128;
static constexpr uint32_t OFF_A0  = 0;
static constexpr uint32_t OFF_A1  = OFF_A0 + TILE_BYTES;
static constexpr uint32_t OFF_B0  = OFF_A1 + TILE_BYTES;
static constexpr uint32_t OFF_B1  = OFF_B0 + TILE_BYTES;
static constexpr uint32_t OFF_SCL = OFF_B1 + TILE_BYTES;
static constexpr uint32_t SMEM_BYTES = OFF_SCL + 512 + 16;
static constexpr uint32_t EPI_ROW_B = 528;

template <int MODE, int KSEG, int NPASS, bool LAST>
__global__ void __launch_bounds__(512, 2)
ctrnn_gemm(const float* __restrict__ sb, float* __restrict__ outp, int gen) {
    extern __shared__ char smem[];
    const uint32_t sbase = smem_u32(smem);
    const int tid  = threadIdx.x;
    const int lane = tid & 31;
    const int wid  = tid >> 5;
    const int warpM = (wid & 3) * 32;
    const int warpN = (wid >> 2) * 32;
    const int rowBase = blockIdx.y * 128;
    const int nBase   = blockIdx.x * 128;

    constexpr int CHPS = KSEG / 64;
    constexpr int NCH  = NPASS * CHPS;

    const __half *Ah, *Al, *Bh;
    if constexpr (MODE == 0)      { Ah = g_Xh;  Al = g_Xl;  Bh = g_Kth; }
    else if constexpr (MODE == 1) { Ah = g_H0h; Al = g_H0l; Bh = g_Rth; }
    else if constexpr (MODE == 2) { Ah = g_HAh; Al = g_HAl; Bh = g_Rth; }
    else if constexpr (MODE == 3) { Ah = g_HBh; Al = g_HBl; Bh = g_Rth; }
    else                          { Ah = g_HAh; Al = g_HAl; Bh = g_Rth; }

    __half *nxh = nullptr, *nxl = nullptr;
    if constexpr (MODE == 1)               { nxh = g_HAh; nxl = g_HAl; }
    else if constexpr (MODE == 2)          { nxh = g_HBh; nxl = g_HBl; }
    else if constexpr (MODE == 3)          { nxh = g_HAh; nxl = g_HAl; }
    else if constexpr (MODE == 4 && !LAST) { nxh = g_H0h; nxl = g_H0l; }

    asm volatile("griddepcontrol.launch_dependents;");

    if (tid < 128)
        reinterpret_cast<float*>(smem + OFF_SCL)[tid] = sb[nBase + tid];

    if (gen > 0) {
        for (int L = tid; L < 1024; L += 512)
            pf_l2(Bh + (size_t)(nBase + (L >> 3)) * KSEG + (L & 7) * 64);
        if (tid < 256)
            pf_l2(g_XKb + (size_t)(rowBase + (tid >> 1)) * UNITS + nBase + (tid & 1) * 64);
        if (tid == 0) {
            const int need = gen * 4;
            while (atomicAdd(&g_flag[blockIdx.y], 0) < need)
                asm volatile("nanosleep.u32 200;");
            __threadfence();
        }
        __syncthreads();
    }

    const __half* Aseg[2] = {Ah, (NPASS == 2) ? Al : Ah};
    const int srow = tid >> 3;
    const int scol = tid & 7;

    auto load_chunk = [&](int c, int buf) {
        const int seg = c / CHPS;
        const int kof = (c % CHPS) * 64;
        const __half* As = Aseg[seg];
        const uint32_t aOff = buf ? OFF_A1 : OFF_A0;
        const uint32_t bOff = buf ? OFF_B1 : OFF_B0;
#pragma unroll
        for (int i = 0; i < 2; ++i) {
            const int r = srow + i * 64;
            uint32_t off = (uint32_t)(r * 128 + ((scol ^ (r & 7)) << 4));
            cp_async16(sbase + aOff + off,
                       As + (size_t)(rowBase + r) * KSEG + kof + scol * 8);
        }
#pragma unroll
        for (int i = 0; i < 2; ++i) {
            const int r = srow + i * 64;
            uint32_t off = (uint32_t)(r * 128 + ((scol ^ (r & 7)) << 4));
            cp_async16(sbase + bOff + off,
                       Bh + (size_t)(nBase + r) * KSEG + kof + scol * 8);
        }
        CP_COMMIT();
    };

    auto pf_f32 = [&](const float* base) {
        const int L = tid;
        pf_l2(base + (size_t)(rowBase + (L >> 2)) * UNITS + nBase + (L & 3) * 32);
    };
    auto pf_f16 = [&](const __half* base) {
        if (tid < 256) {
            const int L = tid;
            pf_l2(base + (size_t)(rowBase + (L >> 1)) * UNITS + nBase + (L & 1) * 64);
        }
    };

    float acc[2][4][4];
#pragma unroll
    for (int mf = 0; mf < 2; ++mf)
#pragma unroll
        for (int nf = 0; nf < 4; ++nf)
#pragma unroll
            for (int i = 0; i < 4; ++i) acc[mf][nf][i] = 0.0f;

    load_chunk(0, 0);

    for (int c = 0; c < NCH; ++c) {
        CP_WAIT(0);
        __syncthreads();
        if (c + 1 < NCH) load_chunk(c + 1, (c + 1) & 1);

        if constexpr (MODE != 0) {
            if (c == NCH - 3) {
                pf_f16(Al);
            } else if (c == NCH - 2) {
                if constexpr (MODE >= 2) pf_f32(g_S);
                if constexpr (MODE == 2 || MODE == 3) { pf_f16(g_H0h); pf_f16(g_H0l); }
            }
        }

        const uint32_t aBase = sbase + ((c & 1) ? OFF_A1 : OFF_A0);
        const uint32_t bBase = sbase + ((c & 1) ? OFF_B1 : OFF_B0);
#pragma unroll
        for (int q = 0; q < 4; ++q) {
            uint32_t a[2][4];
#pragma unroll
            for (int mf = 0; mf < 2; ++mf) {
                const int row = warpM + mf * 16 + ((lane >> 3) & 1) * 8 + (lane & 7);
                const int c16 = q * 2 + (lane >> 4);
                const uint32_t addr = aBase + row * 128 + (((c16 ^ (row & 7)) & 7) << 4);
                ldsm_x4(addr, a[mf][0], a[mf][1], a[mf][2], a[mf][3]);
            }
#pragma unroll
            for (int g = 0; g < 2; ++g) {
                uint32_t b0, b1, b2, b3;
                const int row = warpN + g * 16 + ((lane >> 3) & 1) * 8 + (lane & 7);
                const int c16 = q * 2 + (lane >> 4);
                const uint32_t addr = bBase + row * 128 + (((c16 ^ (row & 7)) & 7) << 4);
                ldsm_x4(addr, b0, b1, b2, b3);
#pragma unroll
                for (int mf = 0; mf < 2; ++mf) {
                    mma16816(acc[mf][2 * g],     a[mf], b0, b2);
                    mma16816(acc[mf][2 * g + 1], a[mf], b1, b3);
                }
            }
        }
    }

    const float* scl = reinterpret_cast<const float*>(smem + OFF_SCL);

    if constexpr (MODE == 0) {
#pragma unroll
        for (int mf = 0; mf < 2; ++mf)
#pragma unroll
            for (int nf = 0; nf < 4; ++nf)
#pragma unroll
                for (int hf = 0; hf < 2; ++hf) {
                    const int row = rowBase + warpM + mf * 16 + (lane >> 2) + hf * 8;
                    const int lc  = warpN + nf * 8 + (lane & 3) * 2;
                    const size_t eb = (size_t)row * UNITS + nBase + lc;
                    const __half2 o = __floats2half2_rn(acc[mf][nf][hf * 2] + scl[lc],
                                                        acc[mf][nf][hf * 2 + 1] + scl[lc + 1]);
                    *reinterpret_cast<__half2*>(g_XKb + eb) = o;
                }
    } else {
#pragma unroll
        for (int p = 0; p < 2; ++p) {
            __syncthreads();
            if (((wid & 3) >> 1) == p) {
                const int rb = warpM - p * 64;
#pragma unroll
                for (int mf = 0; mf < 2; ++mf)
#pragma unroll
                    for (int nf = 0; nf < 4; ++nf)
#pragma unroll
                        for (int hf = 0; hf < 2; ++hf) {
                            const int rloc = rb + mf * 16 + (lane >> 2) + hf * 8;
                            const int lc   = warpN + nf * 8 + (lane & 3) * 2;
                            float2 v;
                            v.x = acc[mf][nf][hf * 2];
                            v.y = acc[mf][nf][hf * 2 + 1];
                            *reinterpret_cast<float2*>(smem + rloc * EPI_ROW_B + lc * 4) = v;
                        }
            }
            __syncthreads();

            const int r   = tid >> 3;
            const int seg = tid & 7;
            const int grow = rowBase + p * 64 + r;
            const int lc0  = seg * 16;
            const size_t ebase = (size_t)grow * UNITS + nBase + lc0;

#pragma unroll
            for (int j = 0; j < 2; ++j) {
                const int lcj = lc0 + j * 8;
                const size_t eb = ebase + j * 8;

                float pre[8];
#pragma unroll
                for (int i = 0; i < 2; ++i) {
                    const float4 v = *reinterpret_cast<const float4*>(
                        smem + r * EPI_ROW_B + (lcj + i * 4) * 4);
                    pre[i * 4 + 0] = v.x; pre[i * 4 + 1] = v.y;
                    pre[i * 4 + 2] = v.z; pre[i * 4 + 3] = v.w;
                }
                __half xk[8], ahv[8], alv[8];
                *reinterpret_cast<uint4*>(xk)  = *reinterpret_cast<const uint4*>(g_XKb + eb);
                *reinterpret_cast<uint4*>(ahv) = *reinterpret_cast<const uint4*>(Ah + eb);
                *reinterpret_cast<uint4*>(alv) = *reinterpret_cast<const uint4*>(Al + eb);

                float hs[8], k[8];
#pragma unroll
                for (int i = 0; i < 8; ++i) {
                    hs[i] = __half2float(ahv[i]) + __half2float(alv[i]);
                    k[i] = scl[lcj + i] * tanh_fast(pre[i] + __half2float(xk[i])) - hs[i];
                }

                if constexpr (MODE == 1) {
                    __half hh[8], hl[8];
                    float sv[8];
#pragma unroll
                    for (int i = 0; i < 8; ++i) {
                        const float hn = hs[i] + DT2 * k[i];
                        hh[i] = __float2half(hn);
                        hl[i] = __float2half(hn - __half2float(hh[i]));
                        sv[i] = hs[i] + DT6 * k[i];
                    }
                    *reinterpret_cast<uint4*>(nxh + eb) = *reinterpret_cast<uint4*>(hh);
                    *reinterpret_cast<uint4*>(nxl + eb) = *reinterpret_cast<uint4*>(hl);
                    *reinterpret_cast<float4*>(g_S + eb)     = make_float4(sv[0], sv[1], sv[2], sv[3]);
                    *reinterpret_cast<float4*>(g_S + eb + 4) = make_float4(sv[4], sv[5], sv[6], sv[7]);
                } else if constexpr (MODE == 2 || MODE == 3) {
                    __half h0h[8], h0l[8];
                    *reinterpret_cast<uint4*>(h0h) = *reinterpret_cast<const uint4*>(g_H0h + eb);
                    *reinterpret_cast<uint4*>(h0l) = *reinterpret_cast<const uint4*>(g_H0l + eb);
                    float sv[8];
                    {
                        const float4 s0 = *reinterpret_cast<const float4*>(g_S + eb);
                        const float4 s1 = *reinterpret_cast<const float4*>(g_S + eb + 4);
                        sv[0] = s0.x; sv[1] = s0.y; sv[2] = s0.z; sv[3] = s0.w;
                        sv[4] = s1.x; sv[5] = s1.y; sv[6] = s1.z; sv[7] = s1.w;
                    }
                    constexpr float HC = (MODE == 2) ? DT2 : DT;
                    __half hh[8], hl[8];
#pragma unroll
                    for (int i = 0; i < 8; ++i) {
                        const float h0v = __half2float(h0h[i]) + __half2float(h0l[i]);
                        const float hn = h0v + HC * k[i];
                        hh[i] = __float2half(hn);
                        hl[i] = __float2half(hn - __half2float(hh[i]));
                        sv[i] += DT3 * k[i];
                    }
                    *reinterpret_cast<uint4*>(nxh + eb) = *reinterpret_cast<uint4*>(hh);
                    *reinterpret_cast<uint4*>(nxl + eb) = *reinterpret_cast<uint4*>(hl);
                    *reinterpret_cast<float4*>(g_S + eb)     = make_float4(sv[0], sv[1], sv[2], sv[3]);
                    *reinterpret_cast<float4*>(g_S + eb + 4) = make_float4(sv[4], sv[5], sv[6], sv[7]);
                } else {
                    float fv[8];
                    {
                        const float4 s0 = *reinterpret_cast<const float4*>(g_S + eb);
                        const float4 s1 = *reinterpret_cast<const float4*>(g_S + eb + 4);
                        fv[0] = s0.x + DT6 * k[0]; fv[1] = s0.y + DT6 * k[1];
                        fv[2] = s0.z + DT6 * k[2]; fv[3] = s0.w + DT6 * k[3];
                        fv[4] = s1.x + DT6 * k[4]; fv[5] = s1.y + DT6 * k[5];
                        fv[6] = s1.z + DT6 * k[6]; fv[7] = s1.w + DT6 * k[7];
                    }
                    if constexpr (LAST) {
                        *reinterpret_cast<float4*>(outp + eb)     = make_float4(fv[0], fv[1], fv[2], fv[3]);
                        *reinterpret_cast<float4*>(outp + eb + 4) = make_float4(fv[4], fv[5], fv[6], fv[7]);
                    } else {
                        __half hh[8], hl[8];
#pragma unroll
                        for (int i = 0; i < 8; ++i) {
                            hh[i] = __float2half(fv[i]);
                            hl[i] = __float2half(fv[i] - __half2float(hh[i]));
                        }
                        *reinterpret_cast<uint4*>(nxh + eb) = *reinterpret_cast<uint4*>(hh);
                        *reinterpret_cast<uint4*>(nxl + eb) = *reinterpret_cast<uint4*>(hl);
                    }
                }
            }
        }
    }

    __threadfence();
    __syncthreads();
    if (tid == 0) atomicAdd(&g_flag[blockIdx.y], 1);
}

__global__ void prep_all_kernel(const float* __restrict__ h, const float* __restrict__ x,
                                const float* __restrict__ Rm, const float* __restrict__ Km) {
    const int i = blockIdx.x * blockDim.x + threadIdx.x;
    if (i < BROWS / 128) g_flag[i] = 0;
    {
        const int nA = BROWS * UNITS / 4;
        if (i < nA) {
            const float4 v = reinterpret_cast<const float4*>(h)[i];
            hsplit2(g_H0h + (size_t)i * 4,     g_H0l + (size_t)i * 4,     v.x, v.y);
            hsplit2(g_H0h + (size_t)i * 4 + 2, g_H0l + (size_t)i * 4 + 2, v.z, v.w);
        }
    }
    {
        const int nB = BROWS * DIN / 4;
        if (i < nB) {
            const float4 v = reinterpret_cast<const float4*>(x)[i];
            hsplit2(g_Xh + (size_t)i * 4,     g_Xl + (size_t)i * 4,     v.x, v.y);
            hsplit2(g_Xh + (size_t)i * 4 + 2, g_Xl + (size_t)i * 4 + 2, v.z, v.w);
        }
    }
    {
        const int nC = UNITS * UNITS;
        if (i < nC) {
            const int k = i / UNITS, n = i % UNITS;
            g_Rth[(size_t)n * UNITS + k] = __float2half(Rm[i]);
        }
    }
    {
        const int nD = DIN * UNITS;
        if (i < nD) {
            const int k = i / UNITS, n = i % UNITS;
            g_Kth[(size_t)n * DIN + k] = __float2half(Km[i]);
        }
    }
}

extern "C" void kernel_launch(void* const* d_in, const int* in_sizes, int n_in,
                              void* d_out, int out_size) {
    const float* x     = (const float*)d_in[0];
    const float* h     = (const float*)d_in[1];
    const float* Km    = (const float*)d_in[2];
    const float* Rm    = (const float*)d_in[3];
    const float* bias  = (const float*)d_in[4];
    const float* scale = (const float*)d_in[5];
    float* out = (float*)d_out;

    cudaFuncSetAttribute(ctrnn_gemm<0, 256, 1, false>, cudaFuncAttributeMaxDynamicSharedMemorySize, SMEM_BYTES);
    cudaFuncSetAttribute(ctrnn_gemm<1, 512, 1, false>, cudaFuncAttributeMaxDynamicSharedMemorySize, SMEM_BYTES);
    cudaFuncSetAttribute(ctrnn_gemm<2, 512, 1, false>, cudaFuncAttributeMaxDynamicSharedMemorySize, SMEM_BYTES);
    cudaFuncSetAttribute(ctrnn_gemm<3, 512, 1, false>, cudaFuncAttributeMaxDynamicSharedMemorySize, SMEM_BYTES);
    cudaFuncSetAttribute(ctrnn_gemm<4, 512, 1, false>, cudaFuncAttributeMaxDynamicSharedMemorySize, SMEM_BYTES);
    cudaFuncSetAttribute(ctrnn_gemm<4, 512, 1, true>,  cudaFuncAttributeMaxDynamicSharedMemorySize, SMEM_BYTES);

    const int nPrep = BROWS * UNITS / 4;
    prep_all_kernel<<<(nPrep + 255) / 256, 256>>>(h, x, Rm, Km);

    const dim3 gg(UNITS / 128, BROWS / 128);

    // mode0: plain launch (ordered after prep by the stream); publishes gen 1
    ctrnn_gemm<0, 256, 1, false><<<gg, 512, SMEM_BYTES>>>(bias, nullptr, 0);

    // stages: PDL launches + per-rowblock flag handshake
    cudaLaunchConfig_t cfg = {};
    cfg.gridDim = gg;
    cfg.blockDim = dim3(512, 1, 1);
    cfg.dynamicSmemBytes = SMEM_BYTES;
    cfg.stream = 0;
    cudaLaunchAttribute at[1];
    at[0].id = cudaLaunchAttributeProgrammaticStreamSerialization;
    at[0].val.programmaticStreamSerializationAllowed = 1;
    cfg.attrs = at;
    cfg.numAttrs = 1;

    int gen = 1;
    for (int u = 0; u < 6; ++u) {
        cudaLaunchKernelEx(&cfg, ctrnn_gemm<1, 512, 1, false>, scale, (float*)nullptr, gen); gen++;
        cudaLaunchKernelEx(&cfg, ctrnn_gemm<2, 512, 1, false>, scale, (float*)nullptr, gen); gen++;
        cudaLaunchKernelEx(&cfg, ctrnn_gemm<3, 512, 1, false>, scale, (float*)nullptr, gen); gen++;
        if (u == 5) cudaLaunchKernelEx(&cfg, ctrnn_gemm<4, 512, 1, true>,  scale, out, gen);
        else        cudaLaunchKernelEx(&cfg, ctrnn_gemm<4, 512, 1, false>, scale, (float*)nullptr, gen);
        gen++;
    }
}